// round 7
// baseline (speedup 1.0000x reference)
#include <cuda_runtime.h>
#include <math.h>

// ---------------- problem constants ----------------
#define BB 2
#define CC 96
#define C2 192
#define HH 256
#define WW 256
#define PIX (HH*WW)          // 65536
#define NP 260               // padded size (256 + 2*2)
#define SW 132               // spectral row stride (131 stored, Hermitian half)
#define NCH (BB*C2)          // 384
#define SPECN_F 67600.0f     // 260*260

// ---------------- scratch (static device globals; no runtime alloc) -------------
__device__ float  g_h1[(size_t)BB*C2*PIX];
__device__ float  g_x2[(size_t)BB*CC*PIX];
__device__ float2 g_spec[(size_t)NCH*260*SW];    // ~105 MB (half-spectrum)
__device__ float  g_mu[(size_t)BB*PIX];          // per-pixel LN mean
__device__ float  g_rs[(size_t)BB*PIX];          // per-pixel LN rsqrt(var+eps)
__device__ float2 g_tw[NP];                      // e^{-2*pi*i*n/260}
__device__ float  g_w9[C2*9];
__device__ float  g_sig[C2];

// compile-time buffer selector: 1=g_h1, 2=g_x2, -1=external pointer
template<int SEL>
__device__ __forceinline__ float* gbuf(const float* ext){
    if (SEL == 1) return g_h1;
    if (SEL == 2) return g_x2;
    return (float*)ext;
}

__device__ __forceinline__ float gelu_f(float x){
    return 0.5f * x * (1.0f + erff(x * 0.70710678118654752440f));
}

// ---------------- complex helpers ----------------
__device__ __forceinline__ float2 cmul(float2 a, float2 b){
    return make_float2(a.x*b.x - a.y*b.y, a.x*b.y + a.y*b.x);
}
__device__ __forceinline__ float2 cmac(float2 s, float2 a, float2 t){
    s.x += a.x*t.x - a.y*t.y;
    s.y += a.x*t.y + a.y*t.x;
    return s;
}
__device__ __forceinline__ float2 cadd(float2 a, float2 b){ return make_float2(a.x+b.x, a.y+b.y); }
__device__ __forceinline__ float2 csub(float2 a, float2 b){ return make_float2(a.x-b.x, a.y-b.y); }

// ---------------- init: twiddles + per-channel softmax/sigma ----------------
__global__ void init_kernel(const float* __restrict__ conv_w,
                            const float* __restrict__ conv_sigma){
    int tid = threadIdx.x;
    if (tid < NP){
        double ang = -2.0 * 3.14159265358979323846 * (double)tid / (double)NP;
        double s, c;
        sincos(ang, &s, &c);
        g_tw[tid] = make_float2((float)c, (float)s);
    }
    for (int ch = tid; ch < C2; ch += blockDim.x){
        float w[9];
        float m = -1e30f;
        #pragma unroll
        for (int i=0;i<9;i++){ w[i] = conv_w[ch*9+i]; m = fmaxf(m, w[i]); }
        float ssum = 0.f;
        #pragma unroll
        for (int i=0;i<9;i++){ w[i] = expf(w[i]-m); ssum += w[i]; }
        float inv = 1.f/ssum;
        #pragma unroll
        for (int i=0;i<9;i++) g_w9[ch*9+i] = w[i]*inv;
        float sp = conv_sigma[ch];
        g_sig[ch] = 1.f/(1.f + expf(9.f - sp)) + 1e-5f;
    }
}

// ---------------- LN statistics: per-pixel mean & rstd over channels ----------------
template<int XSEL>
__global__ void ln_stats(const float* __restrict__ xext){
    const float* x = gbuf<XSEL>(xext);
    int pi = blockIdx.x*blockDim.x + threadIdx.x;
    if (pi >= BB*PIX) return;
    int bb = pi >> 16;
    int p  = pi & (PIX-1);
    const float* xb = x + (size_t)bb*CC*PIX + p;
    float s=0.f, s2=0.f;
    #pragma unroll 4
    for (int c=0;c<CC;c++){ float v = xb[(size_t)c*PIX]; s += v; s2 += v*v; }
    float mu  = s * (1.f/CC);
    float var = s2 * (1.f/CC) - mu*mu;
    g_mu[pi] = mu;
    g_rs[pi] = rsqrtf(var + 1e-5f);
}

// ---------------- 1x1 conv as tiled SGEMM, 8xTN microtile ----------------
// MODE 0: out = gelu(acc + bias);  MODE 1: out = acc + bias + res
// LNIN 1: X element transformed on load: (v - mu[p]) * rs[p] * lnw[c] + lnb[c]
template<int CIN, int COUT, int BN, int TN, int MODE, int LNIN,
         int XSEL, int RSEL, int OSEL>
__global__ void gemm_kernel(const float* __restrict__ Xext,
                            const float* __restrict__ W,
                            const float* __restrict__ bias,
                            const float* __restrict__ lnw,
                            const float* __restrict__ lnb,
                            const float* __restrict__ Rext,
                            float* __restrict__ Oext){
    const float* X   = gbuf<XSEL>(Xext);
    const float* res = gbuf<RSEL>(Rext);
    float*       out = gbuf<OSEL>(Oext);
    const int BM=128, BK=16;
    __shared__ float Xs[BK][BM];
    __shared__ float Ws[BK][BN];
    __shared__ float Ms[BM], Rs[BM];
    int bb = blockIdx.z;
    int p0 = blockIdx.x*BM;
    int o0 = blockIdx.y*BN;
    int tid = threadIdx.x;       // 128
    int tx = tid & 15;           // pixel group (8 px)
    int ty = tid >> 4;           // output group (TN outs)
    float acc[TN][8];
    #pragma unroll
    for (int j=0;j<TN;j++)
        #pragma unroll
        for (int i=0;i<8;i++) acc[j][i]=0.f;

    if (LNIN){
        Ms[tid] = g_mu[(size_t)bb*PIX + p0 + tid];
        Rs[tid] = g_rs[(size_t)bb*PIX + p0 + tid];
        __syncthreads();
    }

    const float* Xb = X + (size_t)bb*CIN*PIX + p0;
    for (int kc=0; kc<CIN; kc+=BK){
        #pragma unroll
        for (int ii=0; ii<4; ii++){
            int idx = tid + 128*ii;
            int k = idx >> 5, c4 = idx & 31;
            float4 v = *(const float4*)(Xb + (size_t)(kc+k)*PIX + c4*4);
            if (LNIN){
                float wk = lnw[kc+k], bk = lnb[kc+k];
                float4 m4 = *(const float4*)&Ms[c4*4];
                float4 r4 = *(const float4*)&Rs[c4*4];
                v.x = (v.x - m4.x)*r4.x*wk + bk;
                v.y = (v.y - m4.y)*r4.y*wk + bk;
                v.z = (v.z - m4.z)*r4.z*wk + bk;
                v.w = (v.w - m4.w)*r4.w*wk + bk;
            }
            *(float4*)&Xs[k][c4*4] = v;
        }
        #pragma unroll
        for (int i=tid; i<BK*BN; i+=128){
            int o = i >> 4, k = i & 15;
            Ws[k][o] = W[(size_t)(o0+o)*CIN + kc + k];
        }
        __syncthreads();
        #pragma unroll
        for (int k=0;k<BK;k++){
            float4 x0 = *(const float4*)&Xs[k][tx*8];
            float4 x1 = *(const float4*)&Xs[k][tx*8+4];
            float xa[8] = {x0.x,x0.y,x0.z,x0.w,x1.x,x1.y,x1.z,x1.w};
            float wa[TN];
            #pragma unroll
            for (int j4=0;j4<TN;j4+=4){
                float4 wv = *(const float4*)&Ws[k][ty*TN + j4];
                wa[j4]=wv.x; wa[j4+1]=wv.y; wa[j4+2]=wv.z; wa[j4+3]=wv.w;
            }
            #pragma unroll
            for (int j=0;j<TN;j++)
                #pragma unroll
                for (int i=0;i<8;i++)
                    acc[j][i] += xa[i]*wa[j];
        }
        __syncthreads();
    }
    #pragma unroll
    for (int j=0;j<TN;j++){
        int o = o0 + ty*TN + j;
        float bj = bias[o];
        size_t oidx = ((size_t)(bb*COUT + o))*PIX + p0 + tx*8;
        float v[8];
        #pragma unroll
        for (int i=0;i<8;i++) v[i] = acc[j][i] + bj;
        if (MODE==0){
            #pragma unroll
            for (int i=0;i<8;i++) v[i] = gelu_f(v[i]);
        } else {
            float4 r0 = *(const float4*)(res + oidx);
            float4 r1 = *(const float4*)(res + oidx + 4);
            v[0]+=r0.x; v[1]+=r0.y; v[2]+=r0.z; v[3]+=r0.w;
            v[4]+=r1.x; v[5]+=r1.y; v[6]+=r1.z; v[7]+=r1.w;
        }
        *(float4*)(out + oidx)     = make_float4(v[0],v[1],v[2],v[3]);
        *(float4*)(out + oidx + 4) = make_float4(v[4],v[5],v[6],v[7]);
    }
}

// ---------------- FFT core: 260 = 20 x 13 (13-pt DFTs then radix-4 20-pt stage) --------
// n = 20a + b (a<13, b<20), k = output index
// Stage A2: A2[13b+k2] = sum_{a<13} z[20a+b] * W13^{a*k2},  W13 = W260^20
// Stage C2: X[k] = sum_b A2[13b + (k%13)] * W260^{b*k}
//   radix-4 over b (W260^65 = -i): quads {q, q+65, q+130, q+195}, q<65 share data.

__device__ __forceinline__ void stageA2(const float2* __restrict__ z,
                                        float2* __restrict__ A2,
                                        const float2* __restrict__ tws,
                                        int lane, int stride, bool inv){
    for (int o=lane;o<NP;o+=stride){
        int b = o/13, k2 = o - 13*b;
        float2 t1 = tws[20*k2];
        if (inv) t1.y = -t1.y;
        float2 t = make_float2(1.f,0.f);
        float2 s = make_float2(0.f,0.f);
        #pragma unroll
        for (int a=0;a<13;a++){
            float2 v = z[20*a + b];
            s = cmac(s, v, t);
            t = cmul(t, t1);
        }
        A2[o] = s;   // o == 13b + k2
    }
}

// compute outputs X[q + 65j], j=0..3
__device__ __forceinline__ void stageC2_quad(const float2* __restrict__ A2,
                                             const float2* __restrict__ tws,
                                             int q, bool inv, float2 X[4]){
    int k2 = q % 13;
    float2 t1 = tws[q]; if (inv) t1.y = -t1.y;
    float2 t2 = cmul(t1,t1);
    float2 u  = cmul(t2,t2);     // t1^4
    float2 S0=make_float2(0,0), S1=make_float2(0,0), S2=make_float2(0,0), S3=make_float2(0,0);
    float2 t = make_float2(1.f,0.f);
    #pragma unroll
    for (int m=0;m<5;m++){
        const float2* base = A2 + (4*m)*13 + k2;
        float2 v0 = base[0], v1 = base[13], v2 = base[26], v3 = base[39];
        S0 = cmac(S0, v0, t);
        S1 = cmac(S1, v1, t);
        S2 = cmac(S2, v2, t);
        S3 = cmac(S3, v3, t);
        t = cmul(t, u);
    }
    float2 T1 = cmul(t1, S1);
    float2 T2 = cmul(t2, S2);
    float2 t3 = cmul(t2, t1);
    float2 T3 = cmul(t3, S3);
    float2 E0 = cadd(S0, T2), E1 = csub(S0, T2);
    float2 O0 = cadd(T1, T3), O1 = csub(T1, T3);
    X[0] = cadd(E0, O0);
    X[2] = csub(E0, O0);
    if (!inv){   // omega = -i
        X[1] = make_float2(E1.x + O1.y, E1.y - O1.x);
        X[3] = make_float2(E1.x - O1.y, E1.y + O1.x);
    } else {     // omega = +i
        X[1] = make_float2(E1.x - O1.y, E1.y + O1.x);
        X[3] = make_float2(E1.x + O1.y, E1.y - O1.x);
    }
}

// ---------------- forward row FFT: two real rows packed per complex FFT ----------------
__global__ void fft_rows_fwd_packed(){
    int pair = blockIdx.x;   // 0..129
    int ch   = blockIdx.y;   // 0..383
    __shared__ float2 xin[NP], As[NP], tws[NP];
    int tid = threadIdx.x;   // 64
    for (int i=tid;i<NP;i+=64) tws[i]=g_tw[i];
    int r0 = 2*pair, r1 = r0+1;
    int s0 = min(max(r0-2,0),HH-1), s1 = min(max(r1-2,0),HH-1);
    const float* p0r = g_h1 + ((size_t)ch*HH + s0)*WW;
    const float* p1r = g_h1 + ((size_t)ch*HH + s1)*WW;
    for (int i=tid;i<NP;i+=64){
        int sc = min(max(i-2,0),WW-1);
        xin[i] = make_float2(p0r[sc], p1r[sc]);
    }
    __syncthreads();
    stageA2(xin, As, tws, tid, 64, false);
    __syncthreads();
    for (int q=tid;q<65;q+=64){
        float2 X[4];
        stageC2_quad(As, tws, q, false, X);
        xin[q]      = X[0];
        xin[q+65]   = X[1];
        xin[q+130]  = X[2];
        xin[q+195]  = X[3];
    }
    __syncthreads();
    float2* o0 = g_spec + ((size_t)ch*260 + r0)*SW;
    float2* o1 = g_spec + ((size_t)ch*260 + r1)*SW;
    for (int k=tid;k<=130;k+=64){
        float2 Zk = xin[k];
        float2 Zm = xin[(260-k)%260];
        // unpack: A=(Z[k]+conj(Z[-k]))/2, B=(Z[k]-conj(Z[-k]))/(2i)
        o0[k] = make_float2(0.5f*(Zk.x+Zm.x), 0.5f*(Zk.y-Zm.y));
        o1[k] = make_float2(0.5f*(Zk.y+Zm.y), 0.5f*(Zm.x-Zk.x));
    }
}

// ---------------- fused column pass: fwd col FFT + filter + inv col FFT ----------------
__global__ void fft_cols_fused(){
    int k0 = blockIdx.x*8;   // 17 blocks cover 131 columns
    int ch = blockIdx.y;
    __shared__ float2 cs[8][NP];
    __shared__ float2 As2[8][NP];
    __shared__ float2 tws[NP];
    __shared__ float ws[10];
    int tid = threadIdx.x;   // 256
    for (int i=tid;i<NP;i+=256) tws[i]=g_tw[i];
    {
        int c2ch = ch % C2;
        if (tid<9) ws[tid]=g_w9[c2ch*9+tid];
        if (tid==9) ws[9]=g_sig[c2ch];
    }
    float2* base = g_spec + (size_t)ch*260*SW + k0;
    int ncols = 131 - k0; if (ncols>8) ncols=8;
    __syncthreads();
    for (int idx=tid; idx<260*8; idx+=256){
        int r=idx>>3, c=idx&7;
        if (c<ncols) cs[c][r] = base[(size_t)r*SW + c];
    }
    __syncthreads();
    int c = tid>>5, lane = tid&31;
    if (c < ncols){
        // ---- forward column FFT ----
        stageA2(cs[c], As2[c], tws, lane, 32, false);
        __syncwarp();
        int k = k0 + c;
        float2 ev = tws[k];
        float2 rp0 = make_float2(ws[0]*ev.x + ws[1] + ws[2]*ev.x, -ws[0]*ev.y + ws[2]*ev.y);
        float2 rp1 = make_float2(ws[3]*ev.x + ws[4] + ws[5]*ev.x, -ws[3]*ev.y + ws[5]*ev.y);
        float2 rp2 = make_float2(ws[6]*ev.x + ws[7] + ws[8]*ev.x, -ws[6]*ev.y + ws[8]*ev.y);
        float sg = ws[9];
        for (int q=lane;q<65;q+=32){
            float2 X[4];
            stageC2_quad(As2[c], tws, q, false, X);
            #pragma unroll
            for (int j=0;j<4;j++){
                int u = q + 65*j;
                float2 eu = tws[u];
                // FB = conj(eu)*rp0 + rp1 + eu*rp2
                float fbx = eu.x*rp0.x + eu.y*rp0.y + rp1.x + eu.x*rp2.x - eu.y*rp2.y;
                float fby = eu.x*rp0.y - eu.y*rp0.x + rp1.y + eu.x*rp2.y + eu.y*rp2.x;
                float denom = fbx*fbx + fby*fby + sg;
                float scale = 1.0f/(SPECN_F*denom);
                float hx = (fbx+sg)*scale, hy = -fby*scale;
                float2 a = X[j];
                cs[c][u] = make_float2(a.x*hx - a.y*hy, a.x*hy + a.y*hx);
            }
        }
        __syncwarp();
        // ---- inverse column FFT ----
        stageA2(cs[c], As2[c], tws, lane, 32, true);
        __syncwarp();
        for (int q=lane;q<65;q+=32){
            float2 X[4];
            stageC2_quad(As2[c], tws, q, true, X);
            cs[c][q]     = X[0];
            cs[c][q+65]  = X[1];
            cs[c][q+130] = X[2];
            cs[c][q+195] = X[3];
        }
    }
    __syncthreads();
    for (int idx=tid; idx<260*8; idx+=256){
        int r=idx>>3, cc=idx&7;
        if (cc<ncols) base[(size_t)r*SW + cc] = cs[cc][r];
    }
}

// ---------------- inverse row FFT: two real output rows per complex inverse FFT --------
// After the fused col pass, spec[ch][u][k] = Y_u[k] (k-spectrum of real spatial row u):
// missing k>130 half from SAME row: Y_u[k] = conj(Y_u[260-k]).
__global__ void fft_rows_inv_packed(){
    int pair = blockIdx.x;   // 0..127
    int ch   = blockIdx.y;
    __shared__ float2 zin[NP], As[NP], tws[NP];
    int tid = threadIdx.x;   // 64
    for (int i=tid;i<NP;i+=64) tws[i]=g_tw[i];
    int u0 = 2 + 2*pair, u1 = u0+1;   // padded output rows
    const float2* su0 = g_spec + ((size_t)ch*260 + u0)*SW;
    const float2* su1 = g_spec + ((size_t)ch*260 + u1)*SW;
    // z[k] = Y_u0[k] + i*Y_u1[k]
    for (int k=tid;k<=130;k+=64){
        float2 a = su0[k], b = su1[k];
        zin[k] = make_float2(a.x - b.y, a.y + b.x);
    }
    for (int k=131+tid;k<260;k+=64){
        float2 a = su0[260-k], b = su1[260-k];
        zin[k] = make_float2(a.x + b.y, b.x - a.y);
    }
    __syncthreads();
    stageA2(zin, As, tws, tid, 64, true);
    __syncthreads();
    for (int q=tid;q<65;q+=64){
        float2 X[4];
        stageC2_quad(As, tws, q, true, X);
        zin[q]     = X[0];
        zin[q+65]  = X[1];
        zin[q+130] = X[2];
        zin[q+195] = X[3];
    }
    __syncthreads();
    float* o0 = g_h1 + ((size_t)ch*HH + (u0-2))*WW;
    float* o1 = g_h1 + ((size_t)ch*HH + (u1-2))*WW;
    for (int jj=tid;jj<WW;jj+=64){
        float2 y = zin[jj+2];
        o0[jj] = gelu_f(y.x);
        o1[jj] = gelu_f(y.y);
    }
}

// ---------------- launcher: kernel launches ONLY ----------------
extern "C" void kernel_launch(void* const* d_in, const int* in_sizes, int n_in,
                              void* d_out, int out_size){
    const float* x         = (const float*)d_in[0];
    const float* ln1_w     = (const float*)d_in[1];
    const float* ln1_b     = (const float*)d_in[2];
    const float* w1a       = (const float*)d_in[3];
    const float* b1a       = (const float*)d_in[4];
    const float* conv_w    = (const float*)d_in[5];
    const float* conv_sig  = (const float*)d_in[6];
    const float* w1b       = (const float*)d_in[7];
    const float* b1b       = (const float*)d_in[8];
    const float* ln2_w     = (const float*)d_in[9];
    const float* ln2_b     = (const float*)d_in[10];
    const float* w2a       = (const float*)d_in[11];
    const float* b2a       = (const float*)d_in[12];
    const float* w2b       = (const float*)d_in[13];
    const float* b2b       = (const float*)d_in[14];
    float* out = (float*)d_out;

    init_kernel<<<1, 260>>>(conv_w, conv_sig);

    // branch 1: LN(stats) -> expand+gelu (LN fused) -> converse2d -> gelu -> project + residual
    ln_stats<-1><<<(BB*PIX)/256, 256>>>(x);
    gemm_kernel<CC, C2, 64, 8, 0, 1, -1, -1, 1><<<dim3(PIX/128, C2/64, BB), 128>>>(
        x, w1a, b1a, ln1_w, ln1_b, nullptr, nullptr);

    fft_rows_fwd_packed<<<dim3(130, NCH), 64>>>();
    fft_cols_fused<<<dim3(17, NCH), 256>>>();
    fft_rows_inv_packed<<<dim3(128, NCH), 64>>>();

    gemm_kernel<C2, CC, 32, 4, 1, 0, 1, -1, 2><<<dim3(PIX/128, CC/32, BB), 128>>>(
        nullptr, w1b, b1b, nullptr, nullptr, x, nullptr);

    // branch 2: LN(stats) -> expand+gelu (LN fused) -> project + residual
    ln_stats<2><<<(BB*PIX)/256, 256>>>(nullptr);
    gemm_kernel<CC, C2, 64, 8, 0, 1, 2, -1, 1><<<dim3(PIX/128, C2/64, BB), 128>>>(
        nullptr, w2a, b2a, ln2_w, ln2_b, nullptr, nullptr);
    gemm_kernel<C2, CC, 32, 4, 1, 0, 1, 2, -1><<<dim3(PIX/128, CC/32, BB), 128>>>(
        nullptr, w2b, b2b, nullptr, nullptr, nullptr, out);
}

// round 8
// speedup vs baseline: 1.1264x; 1.1264x over previous
#include <cuda_runtime.h>
#include <math.h>

// ---------------- problem constants ----------------
#define BB 2
#define CC 96
#define C2 192
#define HH 256
#define WW 256
#define PIX (HH*WW)          // 65536
#define NP 260               // padded size (256 + 2*2)
#define SW 132               // spectral row stride (131 stored, Hermitian half)
#define NCH (BB*C2)          // 384
#define SPECN_F 67600.0f     // 260*260

// ---------------- scratch (static device globals; no runtime alloc) -------------
__device__ float  g_h1[(size_t)BB*C2*PIX];
__device__ float  g_x2[(size_t)BB*CC*PIX];
__device__ float2 g_spec[(size_t)NCH*260*SW];    // ~105 MB (half-spectrum)
__device__ float  g_mu[(size_t)BB*PIX];          // per-pixel LN mean
__device__ float  g_rs[(size_t)BB*PIX];          // per-pixel LN rsqrt(var+eps)
__device__ float2 g_tw[NP];                      // e^{-2*pi*i*n/260}
__device__ float  g_w9[C2*9];
__device__ float  g_sig[C2];

// compile-time buffer selector: 1=g_h1, 2=g_x2, -1=external pointer
template<int SEL>
__device__ __forceinline__ float* gbuf(const float* ext){
    if (SEL == 1) return g_h1;
    if (SEL == 2) return g_x2;
    return (float*)ext;
}

__device__ __forceinline__ float gelu_f(float x){
    return 0.5f * x * (1.0f + erff(x * 0.70710678118654752440f));
}

// ---------------- complex helpers ----------------
__device__ __forceinline__ float2 cmul(float2 a, float2 b){
    return make_float2(a.x*b.x - a.y*b.y, a.x*b.y + a.y*b.x);
}
__device__ __forceinline__ float2 cmac(float2 s, float2 a, float2 t){
    s.x += a.x*t.x - a.y*t.y;
    s.y += a.x*t.y + a.y*t.x;
    return s;
}
__device__ __forceinline__ float2 cadd(float2 a, float2 b){ return make_float2(a.x+b.x, a.y+b.y); }
__device__ __forceinline__ float2 csub(float2 a, float2 b){ return make_float2(a.x-b.x, a.y-b.y); }

// ---------------- init: twiddles + per-channel softmax/sigma ----------------
__global__ void init_kernel(const float* __restrict__ conv_w,
                            const float* __restrict__ conv_sigma){
    int tid = threadIdx.x;
    if (tid < NP){
        double ang = -2.0 * 3.14159265358979323846 * (double)tid / (double)NP;
        double s, c;
        sincos(ang, &s, &c);
        g_tw[tid] = make_float2((float)c, (float)s);
    }
    for (int ch = tid; ch < C2; ch += blockDim.x){
        float w[9];
        float m = -1e30f;
        #pragma unroll
        for (int i=0;i<9;i++){ w[i] = conv_w[ch*9+i]; m = fmaxf(m, w[i]); }
        float ssum = 0.f;
        #pragma unroll
        for (int i=0;i<9;i++){ w[i] = expf(w[i]-m); ssum += w[i]; }
        float inv = 1.f/ssum;
        #pragma unroll
        for (int i=0;i<9;i++) g_w9[ch*9+i] = w[i]*inv;
        float sp = conv_sigma[ch];
        g_sig[ch] = 1.f/(1.f + expf(9.f - sp)) + 1e-5f;
    }
}

// ---------------- LN statistics: per-pixel mean & rstd over channels ----------------
template<int XSEL>
__global__ void ln_stats(const float* __restrict__ xext){
    const float* x = gbuf<XSEL>(xext);
    int pi = blockIdx.x*blockDim.x + threadIdx.x;
    if (pi >= BB*PIX) return;
    int bb = pi >> 16;
    int p  = pi & (PIX-1);
    const float* xb = x + (size_t)bb*CC*PIX + p;
    float s=0.f, s2=0.f;
    #pragma unroll 4
    for (int c=0;c<CC;c++){ float v = xb[(size_t)c*PIX]; s += v; s2 += v*v; }
    float mu  = s * (1.f/CC);
    float var = s2 * (1.f/CC) - mu*mu;
    g_mu[pi] = mu;
    g_rs[pi] = rsqrtf(var + 1e-5f);
}

// ---------------- 1x1 conv as tiled SGEMM, 8xTN microtile (conflict-free LDS) ---------
// MODE 0: out = gelu(acc + bias);  MODE 1: out = acc + bias + res
// LNIN 1: X element transformed on load: (v - mu[p]) * rs[p] * lnw[c] + lnb[c]
// Each thread owns pixels {tx*4..tx*4+3} and {64+tx*4..64+tx*4+3}: 16B-stride
// per 8-thread LDS.128 phase -> conflict-free.
template<int CIN, int COUT, int BN, int TN, int MODE, int LNIN,
         int XSEL, int RSEL, int OSEL>
__global__ void gemm_kernel(const float* __restrict__ Xext,
                            const float* __restrict__ W,
                            const float* __restrict__ bias,
                            const float* __restrict__ lnw,
                            const float* __restrict__ lnb,
                            const float* __restrict__ Rext,
                            float* __restrict__ Oext){
    const float* X   = gbuf<XSEL>(Xext);
    const float* res = gbuf<RSEL>(Rext);
    float*       out = gbuf<OSEL>(Oext);
    const int BM=128, BK=16;
    __shared__ float Xs[BK][BM];
    __shared__ float Ws[BK][BN];
    __shared__ float Ms[BM], Rs[BM];
    int bb = blockIdx.z;
    int p0 = blockIdx.x*BM;
    int o0 = blockIdx.y*BN;
    int tid = threadIdx.x;       // 128
    int tx = tid & 15;           // pixel group
    int ty = tid >> 4;           // output group (TN outs)
    float acc[TN][8];
    #pragma unroll
    for (int j=0;j<TN;j++)
        #pragma unroll
        for (int i=0;i<8;i++) acc[j][i]=0.f;

    if (LNIN){
        Ms[tid] = g_mu[(size_t)bb*PIX + p0 + tid];
        Rs[tid] = g_rs[(size_t)bb*PIX + p0 + tid];
        __syncthreads();
    }

    const float* Xb = X + (size_t)bb*CIN*PIX + p0;
    for (int kc=0; kc<CIN; kc+=BK){
        #pragma unroll
        for (int ii=0; ii<4; ii++){
            int idx = tid + 128*ii;
            int k = idx >> 5, c4 = idx & 31;
            float4 v = *(const float4*)(Xb + (size_t)(kc+k)*PIX + c4*4);
            if (LNIN){
                float wk = lnw[kc+k], bk = lnb[kc+k];
                float4 m4 = *(const float4*)&Ms[c4*4];
                float4 r4 = *(const float4*)&Rs[c4*4];
                v.x = (v.x - m4.x)*r4.x*wk + bk;
                v.y = (v.y - m4.y)*r4.y*wk + bk;
                v.z = (v.z - m4.z)*r4.z*wk + bk;
                v.w = (v.w - m4.w)*r4.w*wk + bk;
            }
            *(float4*)&Xs[k][c4*4] = v;
        }
        #pragma unroll
        for (int i=tid; i<BK*BN; i+=128){
            int o = i >> 4, k = i & 15;
            Ws[k][o] = W[(size_t)(o0+o)*CIN + kc + k];
        }
        __syncthreads();
        #pragma unroll
        for (int k=0;k<BK;k++){
            float4 x0 = *(const float4*)&Xs[k][tx*4];        // conflict-free
            float4 x1 = *(const float4*)&Xs[k][64 + tx*4];   // conflict-free
            float xa[8] = {x0.x,x0.y,x0.z,x0.w,x1.x,x1.y,x1.z,x1.w};
            float wa[TN];
            #pragma unroll
            for (int j4=0;j4<TN;j4+=4){
                float4 wv = *(const float4*)&Ws[k][ty*TN + j4];
                wa[j4]=wv.x; wa[j4+1]=wv.y; wa[j4+2]=wv.z; wa[j4+3]=wv.w;
            }
            #pragma unroll
            for (int j=0;j<TN;j++)
                #pragma unroll
                for (int i=0;i<8;i++)
                    acc[j][i] += xa[i]*wa[j];
        }
        __syncthreads();
    }
    #pragma unroll
    for (int j=0;j<TN;j++){
        int o = o0 + ty*TN + j;
        float bj = bias[o];
        size_t ob = ((size_t)(bb*COUT + o))*PIX + p0;
        size_t oidx0 = ob + tx*4;
        size_t oidx1 = ob + 64 + tx*4;
        float v[8];
        #pragma unroll
        for (int i=0;i<8;i++) v[i] = acc[j][i] + bj;
        if (MODE==0){
            #pragma unroll
            for (int i=0;i<8;i++) v[i] = gelu_f(v[i]);
        } else {
            float4 r0 = *(const float4*)(res + oidx0);
            float4 r1 = *(const float4*)(res + oidx1);
            v[0]+=r0.x; v[1]+=r0.y; v[2]+=r0.z; v[3]+=r0.w;
            v[4]+=r1.x; v[5]+=r1.y; v[6]+=r1.z; v[7]+=r1.w;
        }
        *(float4*)(out + oidx0) = make_float4(v[0],v[1],v[2],v[3]);
        *(float4*)(out + oidx1) = make_float4(v[4],v[5],v[6],v[7]);
    }
}

// ---------------- FFT core: 260 = 20 x 13 (13-pt DFTs then radix-4 20-pt stage) --------
// n = 20a + b (a<13, b<20), k = output index
// Stage A2: A2[13b+k2] = sum_{a<13} z[20a+b] * W13^{a*k2},  W13 = W260^20
// Stage C2: X[k] = sum_b A2[13b + (k%13)] * W260^{b*k}
//   radix-4 over b (W260^65 = -i): quads {q, q+65, q+130, q+195}, q<65 share data.

__device__ __forceinline__ void stageA2(const float2* __restrict__ z,
                                        float2* __restrict__ A2,
                                        const float2* __restrict__ tws,
                                        int lane, int stride, bool inv){
    for (int o=lane;o<NP;o+=stride){
        int b = o/13, k2 = o - 13*b;
        float2 t1 = tws[20*k2];
        if (inv) t1.y = -t1.y;
        float2 t = make_float2(1.f,0.f);
        float2 s = make_float2(0.f,0.f);
        #pragma unroll
        for (int a=0;a<13;a++){
            float2 v = z[20*a + b];
            s = cmac(s, v, t);
            t = cmul(t, t1);
        }
        A2[o] = s;   // o == 13b + k2
    }
}

// compute outputs X[q + 65j], j=0..3
__device__ __forceinline__ void stageC2_quad(const float2* __restrict__ A2,
                                             const float2* __restrict__ tws,
                                             int q, bool inv, float2 X[4]){
    int k2 = q % 13;
    float2 t1 = tws[q]; if (inv) t1.y = -t1.y;
    float2 t2 = cmul(t1,t1);
    float2 u  = cmul(t2,t2);     // t1^4
    float2 S0=make_float2(0,0), S1=make_float2(0,0), S2=make_float2(0,0), S3=make_float2(0,0);
    float2 t = make_float2(1.f,0.f);
    #pragma unroll
    for (int m=0;m<5;m++){
        const float2* base = A2 + (4*m)*13 + k2;
        float2 v0 = base[0], v1 = base[13], v2 = base[26], v3 = base[39];
        S0 = cmac(S0, v0, t);
        S1 = cmac(S1, v1, t);
        S2 = cmac(S2, v2, t);
        S3 = cmac(S3, v3, t);
        t = cmul(t, u);
    }
    float2 T1 = cmul(t1, S1);
    float2 T2 = cmul(t2, S2);
    float2 t3 = cmul(t2, t1);
    float2 T3 = cmul(t3, S3);
    float2 E0 = cadd(S0, T2), E1 = csub(S0, T2);
    float2 O0 = cadd(T1, T3), O1 = csub(T1, T3);
    X[0] = cadd(E0, O0);
    X[2] = csub(E0, O0);
    if (!inv){   // omega = -i
        X[1] = make_float2(E1.x + O1.y, E1.y - O1.x);
        X[3] = make_float2(E1.x - O1.y, E1.y + O1.x);
    } else {     // omega = +i
        X[1] = make_float2(E1.x - O1.y, E1.y + O1.x);
        X[3] = make_float2(E1.x + O1.y, E1.y - O1.x);
    }
}

// ---------------- forward row FFT: two real rows packed per complex FFT ----------------
__global__ void fft_rows_fwd_packed(){
    int pair = blockIdx.x;   // 0..129
    int ch   = blockIdx.y;   // 0..383
    __shared__ float2 xin[NP], As[NP], tws[NP];
    int tid = threadIdx.x;   // 64
    for (int i=tid;i<NP;i+=64) tws[i]=g_tw[i];
    int r0 = 2*pair, r1 = r0+1;
    int s0 = min(max(r0-2,0),HH-1), s1 = min(max(r1-2,0),HH-1);
    const float* p0r = g_h1 + ((size_t)ch*HH + s0)*WW;
    const float* p1r = g_h1 + ((size_t)ch*HH + s1)*WW;
    for (int i=tid;i<NP;i+=64){
        int sc = min(max(i-2,0),WW-1);
        xin[i] = make_float2(p0r[sc], p1r[sc]);
    }
    __syncthreads();
    stageA2(xin, As, tws, tid, 64, false);
    __syncthreads();
    for (int q=tid;q<65;q+=64){
        float2 X[4];
        stageC2_quad(As, tws, q, false, X);
        xin[q]      = X[0];
        xin[q+65]   = X[1];
        xin[q+130]  = X[2];
        xin[q+195]  = X[3];
    }
    __syncthreads();
    float2* o0 = g_spec + ((size_t)ch*260 + r0)*SW;
    float2* o1 = g_spec + ((size_t)ch*260 + r1)*SW;
    for (int k=tid;k<=130;k+=64){
        float2 Zk = xin[k];
        float2 Zm = xin[(260-k)%260];
        // unpack: A=(Z[k]+conj(Z[-k]))/2, B=(Z[k]-conj(Z[-k]))/(2i)
        o0[k] = make_float2(0.5f*(Zk.x+Zm.x), 0.5f*(Zk.y-Zm.y));
        o1[k] = make_float2(0.5f*(Zk.y+Zm.y), 0.5f*(Zm.x-Zk.x));
    }
}

// ---------------- fused column pass: fwd col FFT + filter + inv col FFT ----------------
__global__ void fft_cols_fused(){
    int k0 = blockIdx.x*8;   // 17 blocks cover 131 columns
    int ch = blockIdx.y;
    __shared__ float2 cs[8][NP];
    __shared__ float2 As2[8][NP];
    __shared__ float2 tws[NP];
    __shared__ float ws[10];
    int tid = threadIdx.x;   // 256
    for (int i=tid;i<NP;i+=256) tws[i]=g_tw[i];
    {
        int c2ch = ch % C2;
        if (tid<9) ws[tid]=g_w9[c2ch*9+tid];
        if (tid==9) ws[9]=g_sig[c2ch];
    }
    float2* base = g_spec + (size_t)ch*260*SW + k0;
    int ncols = 131 - k0; if (ncols>8) ncols=8;
    __syncthreads();
    for (int idx=tid; idx<260*8; idx+=256){
        int r=idx>>3, c=idx&7;
        if (c<ncols) cs[c][r] = base[(size_t)r*SW + c];
    }
    __syncthreads();
    int c = tid>>5, lane = tid&31;
    if (c < ncols){
        // ---- forward column FFT ----
        stageA2(cs[c], As2[c], tws, lane, 32, false);
        __syncwarp();
        int k = k0 + c;
        float2 ev = tws[k];
        float2 rp0 = make_float2(ws[0]*ev.x + ws[1] + ws[2]*ev.x, -ws[0]*ev.y + ws[2]*ev.y);
        float2 rp1 = make_float2(ws[3]*ev.x + ws[4] + ws[5]*ev.x, -ws[3]*ev.y + ws[5]*ev.y);
        float2 rp2 = make_float2(ws[6]*ev.x + ws[7] + ws[8]*ev.x, -ws[6]*ev.y + ws[8]*ev.y);
        float sg = ws[9];
        for (int q=lane;q<65;q+=32){
            float2 X[4];
            stageC2_quad(As2[c], tws, q, false, X);
            #pragma unroll
            for (int j=0;j<4;j++){
                int u = q + 65*j;
                float2 eu = tws[u];
                // FB = conj(eu)*rp0 + rp1 + eu*rp2
                float fbx = eu.x*rp0.x + eu.y*rp0.y + rp1.x + eu.x*rp2.x - eu.y*rp2.y;
                float fby = eu.x*rp0.y - eu.y*rp0.x + rp1.y + eu.x*rp2.y + eu.y*rp2.x;
                float denom = fbx*fbx + fby*fby + sg;
                float scale = 1.0f/(SPECN_F*denom);
                float hx = (fbx+sg)*scale, hy = -fby*scale;
                float2 a = X[j];
                cs[c][u] = make_float2(a.x*hx - a.y*hy, a.x*hy + a.y*hx);
            }
        }
        __syncwarp();
        // ---- inverse column FFT ----
        stageA2(cs[c], As2[c], tws, lane, 32, true);
        __syncwarp();
        for (int q=lane;q<65;q+=32){
            float2 X[4];
            stageC2_quad(As2[c], tws, q, true, X);
            cs[c][q]     = X[0];
            cs[c][q+65]  = X[1];
            cs[c][q+130] = X[2];
            cs[c][q+195] = X[3];
        }
    }
    __syncthreads();
    for (int idx=tid; idx<260*8; idx+=256){
        int r=idx>>3, cc=idx&7;
        if (cc<ncols) base[(size_t)r*SW + cc] = cs[cc][r];
    }
}

// ---------------- inverse row FFT: two real output rows per complex inverse FFT --------
// After the fused col pass, spec[ch][u][k] = Y_u[k] (k-spectrum of real spatial row u):
// missing k>130 half from SAME row: Y_u[k] = conj(Y_u[260-k]).
__global__ void fft_rows_inv_packed(){
    int pair = blockIdx.x;   // 0..127
    int ch   = blockIdx.y;
    __shared__ float2 zin[NP], As[NP], tws[NP];
    int tid = threadIdx.x;   // 64
    for (int i=tid;i<NP;i+=64) tws[i]=g_tw[i];
    int u0 = 2 + 2*pair, u1 = u0+1;   // padded output rows
    const float2* su0 = g_spec + ((size_t)ch*260 + u0)*SW;
    const float2* su1 = g_spec + ((size_t)ch*260 + u1)*SW;
    // z[k] = Y_u0[k] + i*Y_u1[k]
    for (int k=tid;k<=130;k+=64){
        float2 a = su0[k], b = su1[k];
        zin[k] = make_float2(a.x - b.y, a.y + b.x);
    }
    for (int k=131+tid;k<260;k+=64){
        float2 a = su0[260-k], b = su1[260-k];
        zin[k] = make_float2(a.x + b.y, b.x - a.y);
    }
    __syncthreads();
    stageA2(zin, As, tws, tid, 64, true);
    __syncthreads();
    for (int q=tid;q<65;q+=64){
        float2 X[4];
        stageC2_quad(As, tws, q, true, X);
        zin[q]     = X[0];
        zin[q+65]  = X[1];
        zin[q+130] = X[2];
        zin[q+195] = X[3];
    }
    __syncthreads();
    float* o0 = g_h1 + ((size_t)ch*HH + (u0-2))*WW;
    float* o1 = g_h1 + ((size_t)ch*HH + (u1-2))*WW;
    for (int jj=tid;jj<WW;jj+=64){
        float2 y = zin[jj+2];
        o0[jj] = gelu_f(y.x);
        o1[jj] = gelu_f(y.y);
    }
}

// ---------------- launcher: kernel launches ONLY ----------------
extern "C" void kernel_launch(void* const* d_in, const int* in_sizes, int n_in,
                              void* d_out, int out_size){
    const float* x         = (const float*)d_in[0];
    const float* ln1_w     = (const float*)d_in[1];
    const float* ln1_b     = (const float*)d_in[2];
    const float* w1a       = (const float*)d_in[3];
    const float* b1a       = (const float*)d_in[4];
    const float* conv_w    = (const float*)d_in[5];
    const float* conv_sig  = (const float*)d_in[6];
    const float* w1b       = (const float*)d_in[7];
    const float* b1b       = (const float*)d_in[8];
    const float* ln2_w     = (const float*)d_in[9];
    const float* ln2_b     = (const float*)d_in[10];
    const float* w2a       = (const float*)d_in[11];
    const float* b2a       = (const float*)d_in[12];
    const float* w2b       = (const float*)d_in[13];
    const float* b2b       = (const float*)d_in[14];
    float* out = (float*)d_out;

    init_kernel<<<1, 260>>>(conv_w, conv_sig);

    // branch 1: LN(stats) -> expand+gelu (LN fused) -> converse2d -> gelu -> project + residual
    ln_stats<-1><<<(BB*PIX)/256, 256>>>(x);
    gemm_kernel<CC, C2, 64, 8, 0, 1, -1, -1, 1><<<dim3(PIX/128, C2/64, BB), 128>>>(
        x, w1a, b1a, ln1_w, ln1_b, nullptr, nullptr);

    fft_rows_fwd_packed<<<dim3(130, NCH), 64>>>();
    fft_cols_fused<<<dim3(17, NCH), 256>>>();
    fft_rows_inv_packed<<<dim3(128, NCH), 64>>>();

    gemm_kernel<C2, CC, 32, 4, 1, 0, 1, -1, 2><<<dim3(PIX/128, CC/32, BB), 128>>>(
        nullptr, w1b, b1b, nullptr, nullptr, x, nullptr);

    // branch 2: LN(stats) -> expand+gelu (LN fused) -> project + residual
    ln_stats<2><<<(BB*PIX)/256, 256>>>(nullptr);
    gemm_kernel<CC, C2, 64, 8, 0, 1, 2, -1, 1><<<dim3(PIX/128, C2/64, BB), 128>>>(
        nullptr, w2a, b2a, ln2_w, ln2_b, nullptr, nullptr);
    gemm_kernel<C2, CC, 32, 4, 1, 0, 1, 2, -1><<<dim3(PIX/128, CC/32, BB), 128>>>(
        nullptr, w2b, b2b, nullptr, nullptr, nullptr, out);
}

// round 10
// speedup vs baseline: 1.1649x; 1.0342x over previous
#include <cuda_runtime.h>
#include <math.h>

// ---------------- problem constants ----------------
#define BB 2
#define CC 96
#define C2 192
#define HH 256
#define WW 256
#define PIX (HH*WW)          // 65536
#define NP 260               // padded size (256 + 2*2)
#define SW 132               // spectral row stride (131 stored, Hermitian half)
#define NCH (BB*C2)          // 384
#define SPECN_F 67600.0f     // 260*260

// ---------------- scratch (static device globals; no runtime alloc) -------------
__device__ float  g_h1[(size_t)BB*C2*PIX];
__device__ float  g_x2[(size_t)BB*CC*PIX];
__device__ float2 g_spec[(size_t)NCH*260*SW];    // ~105 MB (half-spectrum)
__device__ float  g_mu[(size_t)BB*PIX];          // per-pixel LN mean
__device__ float  g_rs[(size_t)BB*PIX];          // per-pixel LN rsqrt(var+eps)
__device__ float2 g_tw[NP];                      // e^{-2*pi*i*n/260}
__device__ float  g_w9[C2*9];
__device__ float  g_sig[C2];

// compile-time buffer selector: 1=g_h1, 2=g_x2, -1=external pointer
template<int SEL>
__device__ __forceinline__ float* gbuf(const float* ext){
    if (SEL == 1) return g_h1;
    if (SEL == 2) return g_x2;
    return (float*)ext;
}

__device__ __forceinline__ float gelu_f(float x){
    return 0.5f * x * (1.0f + erff(x * 0.70710678118654752440f));
}

// ---------------- complex helpers ----------------
__device__ __forceinline__ float2 cmul(float2 a, float2 b){
    return make_float2(a.x*b.x - a.y*b.y, a.x*b.y + a.y*b.x);
}
__device__ __forceinline__ float2 cmac(float2 s, float2 a, float2 t){
    s.x += a.x*t.x - a.y*t.y;
    s.y += a.x*t.y + a.y*t.x;
    return s;
}
__device__ __forceinline__ float2 cadd(float2 a, float2 b){ return make_float2(a.x+b.x, a.y+b.y); }
__device__ __forceinline__ float2 csub(float2 a, float2 b){ return make_float2(a.x-b.x, a.y-b.y); }

// ---------------- init: twiddles + per-channel softmax/sigma ----------------
__global__ void init_kernel(const float* __restrict__ conv_w,
                            const float* __restrict__ conv_sigma){
    int tid = threadIdx.x;
    if (tid < NP){
        double ang = -2.0 * 3.14159265358979323846 * (double)tid / (double)NP;
        double s, c;
        sincos(ang, &s, &c);
        g_tw[tid] = make_float2((float)c, (float)s);
    }
    for (int ch = tid; ch < C2; ch += blockDim.x){
        float w[9];
        float m = -1e30f;
        #pragma unroll
        for (int i=0;i<9;i++){ w[i] = conv_w[ch*9+i]; m = fmaxf(m, w[i]); }
        float ssum = 0.f;
        #pragma unroll
        for (int i=0;i<9;i++){ w[i] = expf(w[i]-m); ssum += w[i]; }
        float inv = 1.f/ssum;
        #pragma unroll
        for (int i=0;i<9;i++) g_w9[ch*9+i] = w[i]*inv;
        float sp = conv_sigma[ch];
        g_sig[ch] = 1.f/(1.f + expf(9.f - sp)) + 1e-5f;
    }
}

// ---------------- LN statistics: per-pixel mean & rstd over channels ----------------
template<int XSEL>
__global__ void ln_stats(const float* __restrict__ xext){
    const float* x = gbuf<XSEL>(xext);
    int pi = blockIdx.x*blockDim.x + threadIdx.x;
    if (pi >= BB*PIX) return;
    int bb = pi >> 16;
    int p  = pi & (PIX-1);
    const float* xb = x + (size_t)bb*CC*PIX + p;
    float s=0.f, s2=0.f;
    #pragma unroll 4
    for (int c=0;c<CC;c++){ float v = xb[(size_t)c*PIX]; s += v; s2 += v*v; }
    float mu  = s * (1.f/CC);
    float var = s2 * (1.f/CC) - mu*mu;
    g_mu[pi] = mu;
    g_rs[pi] = rsqrtf(var + 1e-5f);
}

// ---------------- 1x1 conv as tiled SGEMM, 8xTN microtile (conflict-free LDS) ---------
// MODE 0: out = gelu(acc + bias);  MODE 1: out = acc + bias + res
// LNIN 1: X element transformed on load: (v - mu[p]) * rs[p] * lnw[c] + lnb[c]
template<int CIN, int COUT, int BN, int TN, int MODE, int LNIN,
         int XSEL, int RSEL, int OSEL>
__global__ void gemm_kernel(const float* __restrict__ Xext,
                            const float* __restrict__ W,
                            const float* __restrict__ bias,
                            const float* __restrict__ lnw,
                            const float* __restrict__ lnb,
                            const float* __restrict__ Rext,
                            float* __restrict__ Oext){
    const float* X   = gbuf<XSEL>(Xext);
    const float* res = gbuf<RSEL>(Rext);
    float*       out = gbuf<OSEL>(Oext);
    const int BM=128, BK=16;
    __shared__ float Xs[BK][BM];
    __shared__ float Ws[BK][BN];
    __shared__ float Ms[BM], Rs[BM];
    int bb = blockIdx.z;
    int p0 = blockIdx.x*BM;
    int o0 = blockIdx.y*BN;
    int tid = threadIdx.x;       // 128
    int tx = tid & 15;           // pixel group
    int ty = tid >> 4;           // output group (TN outs)
    float acc[TN][8];
    #pragma unroll
    for (int j=0;j<TN;j++)
        #pragma unroll
        for (int i=0;i<8;i++) acc[j][i]=0.f;

    if (LNIN){
        Ms[tid] = g_mu[(size_t)bb*PIX + p0 + tid];
        Rs[tid] = g_rs[(size_t)bb*PIX + p0 + tid];
        __syncthreads();
    }

    const float* Xb = X + (size_t)bb*CIN*PIX + p0;
    for (int kc=0; kc<CIN; kc+=BK){
        #pragma unroll
        for (int ii=0; ii<4; ii++){
            int idx = tid + 128*ii;
            int k = idx >> 5, c4 = idx & 31;
            float4 v = *(const float4*)(Xb + (size_t)(kc+k)*PIX + c4*4);
            if (LNIN){
                float wk = lnw[kc+k], bk = lnb[kc+k];
                float4 m4 = *(const float4*)&Ms[c4*4];
                float4 r4 = *(const float4*)&Rs[c4*4];
                v.x = (v.x - m4.x)*r4.x*wk + bk;
                v.y = (v.y - m4.y)*r4.y*wk + bk;
                v.z = (v.z - m4.z)*r4.z*wk + bk;
                v.w = (v.w - m4.w)*r4.w*wk + bk;
            }
            *(float4*)&Xs[k][c4*4] = v;
        }
        #pragma unroll
        for (int i=tid; i<BK*BN; i+=128){
            int o = i >> 4, k = i & 15;
            Ws[k][o] = W[(size_t)(o0+o)*CIN + kc + k];
        }
        __syncthreads();
        #pragma unroll
        for (int k=0;k<BK;k++){
            float4 x0 = *(const float4*)&Xs[k][tx*4];        // conflict-free
            float4 x1 = *(const float4*)&Xs[k][64 + tx*4];   // conflict-free
            float xa[8] = {x0.x,x0.y,x0.z,x0.w,x1.x,x1.y,x1.z,x1.w};
            float wa[TN];
            #pragma unroll
            for (int j4=0;j4<TN;j4+=4){
                float4 wv = *(const float4*)&Ws[k][ty*TN + j4];
                wa[j4]=wv.x; wa[j4+1]=wv.y; wa[j4+2]=wv.z; wa[j4+3]=wv.w;
            }
            #pragma unroll
            for (int j=0;j<TN;j++)
                #pragma unroll
                for (int i=0;i<8;i++)
                    acc[j][i] += xa[i]*wa[j];
        }
        __syncthreads();
    }
    #pragma unroll
    for (int j=0;j<TN;j++){
        int o = o0 + ty*TN + j;
        float bj = bias[o];
        size_t ob = ((size_t)(bb*COUT + o))*PIX + p0;
        size_t oidx0 = ob + tx*4;
        size_t oidx1 = ob + 64 + tx*4;
        float v[8];
        #pragma unroll
        for (int i=0;i<8;i++) v[i] = acc[j][i] + bj;
        if (MODE==0){
            #pragma unroll
            for (int i=0;i<8;i++) v[i] = gelu_f(v[i]);
        } else {
            float4 r0 = *(const float4*)(res + oidx0);
            float4 r1 = *(const float4*)(res + oidx1);
            v[0]+=r0.x; v[1]+=r0.y; v[2]+=r0.z; v[3]+=r0.w;
            v[4]+=r1.x; v[5]+=r1.y; v[6]+=r1.z; v[7]+=r1.w;
        }
        *(float4*)(out + oidx0) = make_float4(v[0],v[1],v[2],v[3]);
        *(float4*)(out + oidx1) = make_float4(v[4],v[5],v[6],v[7]);
    }
}

// ---------------- FFT core: 260 = 20 x 13 (13-pt DFTs then radix-4 20-pt stage) --------
__device__ __forceinline__ void stageA2(const float2* __restrict__ z,
                                        float2* __restrict__ A2,
                                        const float2* __restrict__ tws,
                                        int lane, int stride, bool inv){
    for (int o=lane;o<NP;o+=stride){
        int b = o/13, k2 = o - 13*b;
        float2 t1 = tws[20*k2];
        if (inv) t1.y = -t1.y;
        float2 t = make_float2(1.f,0.f);
        float2 s = make_float2(0.f,0.f);
        #pragma unroll
        for (int a=0;a<13;a++){
            float2 v = z[20*a + b];
            s = cmac(s, v, t);
            t = cmul(t, t1);
        }
        A2[o] = s;   // o == 13b + k2
    }
}

// compute outputs X[q + 65j], j=0..3
__device__ __forceinline__ void stageC2_quad(const float2* __restrict__ A2,
                                             const float2* __restrict__ tws,
                                             int q, bool inv, float2 X[4]){
    int k2 = q % 13;
    float2 t1 = tws[q]; if (inv) t1.y = -t1.y;
    float2 t2 = cmul(t1,t1);
    float2 u  = cmul(t2,t2);     // t1^4
    float2 S0=make_float2(0,0), S1=make_float2(0,0), S2=make_float2(0,0), S3=make_float2(0,0);
    float2 t = make_float2(1.f,0.f);
    #pragma unroll
    for (int m=0;m<5;m++){
        const float2* base = A2 + (4*m)*13 + k2;
        float2 v0 = base[0], v1 = base[13], v2 = base[26], v3 = base[39];
        S0 = cmac(S0, v0, t);
        S1 = cmac(S1, v1, t);
        S2 = cmac(S2, v2, t);
        S3 = cmac(S3, v3, t);
        t = cmul(t, u);
    }
    float2 T1 = cmul(t1, S1);
    float2 T2 = cmul(t2, S2);
    float2 t3 = cmul(t2, t1);
    float2 T3 = cmul(t3, S3);
    float2 E0 = cadd(S0, T2), E1 = csub(S0, T2);
    float2 O0 = cadd(T1, T3), O1 = csub(T1, T3);
    X[0] = cadd(E0, O0);
    X[2] = csub(E0, O0);
    if (!inv){   // omega = -i
        X[1] = make_float2(E1.x + O1.y, E1.y - O1.x);
        X[3] = make_float2(E1.x - O1.y, E1.y + O1.x);
    } else {     // omega = +i
        X[1] = make_float2(E1.x - O1.y, E1.y + O1.x);
        X[3] = make_float2(E1.x + O1.y, E1.y - O1.x);
    }
}

// ---------------- forward row FFT: warp-per-transform, 8 transforms/block --------------
// 130*384 = 49920 row-pair transforms, 8 per block -> 6240 blocks.
__global__ __launch_bounds__(256) void fft_rows_fwd_packed(){
    __shared__ float2 xin[8][NP], As[8][NP], tws[NP];
    int tid = threadIdx.x;
    int w = tid >> 5, lane = tid & 31;
    for (int i=tid;i<NP;i+=256) tws[i]=g_tw[i];
    __syncthreads();
    int g = blockIdx.x*8 + w;
    int ch = g/130, pair = g - 130*ch;
    int r0 = 2*pair, r1 = r0+1;
    int s0 = min(max(r0-2,0),HH-1), s1 = min(max(r1-2,0),HH-1);
    const float* p0r = g_h1 + ((size_t)ch*HH + s0)*WW;
    const float* p1r = g_h1 + ((size_t)ch*HH + s1)*WW;
    float2* xw = xin[w];
    float2* Aw = As[w];
    for (int i=lane;i<NP;i+=32){
        int sc = min(max(i-2,0),WW-1);
        xw[i] = make_float2(p0r[sc], p1r[sc]);
    }
    __syncwarp();
    stageA2(xw, Aw, tws, lane, 32, false);
    __syncwarp();
    for (int q=lane;q<65;q+=32){
        float2 X[4];
        stageC2_quad(Aw, tws, q, false, X);
        xw[q]      = X[0];
        xw[q+65]   = X[1];
        xw[q+130]  = X[2];
        xw[q+195]  = X[3];
    }
    __syncwarp();
    float2* o0 = g_spec + ((size_t)ch*260 + r0)*SW;
    float2* o1 = g_spec + ((size_t)ch*260 + r1)*SW;
    for (int k=lane;k<=130;k+=32){
        float2 Zk = xw[k];
        float2 Zm = xw[(260-k)%260];
        // unpack: A=(Z[k]+conj(Z[-k]))/2, B=(Z[k]-conj(Z[-k]))/(2i)
        o0[k] = make_float2(0.5f*(Zk.x+Zm.x), 0.5f*(Zk.y-Zm.y));
        o1[k] = make_float2(0.5f*(Zk.y+Zm.y), 0.5f*(Zm.x-Zk.x));
    }
}

// ---------------- fused column pass: fwd col FFT + filter + inv col FFT ----------------
__global__ void fft_cols_fused(){
    int k0 = blockIdx.x*8;   // 17 blocks cover 131 columns
    int ch = blockIdx.y;
    __shared__ float2 cs[8][NP];
    __shared__ float2 As2[8][NP];
    __shared__ float2 tws[NP];
    __shared__ float ws[10];
    int tid = threadIdx.x;   // 256
    for (int i=tid;i<NP;i+=256) tws[i]=g_tw[i];
    {
        int c2ch = ch % C2;
        if (tid<9) ws[tid]=g_w9[c2ch*9+tid];
        if (tid==9) ws[9]=g_sig[c2ch];
    }
    float2* base = g_spec + (size_t)ch*260*SW + k0;
    int ncols = 131 - k0; if (ncols>8) ncols=8;
    __syncthreads();
    for (int idx=tid; idx<260*8; idx+=256){
        int r=idx>>3, c=idx&7;
        if (c<ncols) cs[c][r] = base[(size_t)r*SW + c];
    }
    __syncthreads();
    int c = tid>>5, lane = tid&31;
    if (c < ncols){
        // ---- forward column FFT ----
        stageA2(cs[c], As2[c], tws, lane, 32, false);
        __syncwarp();
        int k = k0 + c;
        float2 ev = tws[k];
        float2 rp0 = make_float2(ws[0]*ev.x + ws[1] + ws[2]*ev.x, -ws[0]*ev.y + ws[2]*ev.y);
        float2 rp1 = make_float2(ws[3]*ev.x + ws[4] + ws[5]*ev.x, -ws[3]*ev.y + ws[5]*ev.y);
        float2 rp2 = make_float2(ws[6]*ev.x + ws[7] + ws[8]*ev.x, -ws[6]*ev.y + ws[8]*ev.y);
        float sg = ws[9];
        for (int q=lane;q<65;q+=32){
            float2 X[4];
            stageC2_quad(As2[c], tws, q, false, X);
            #pragma unroll
            for (int j=0;j<4;j++){
                int u = q + 65*j;
                float2 eu = tws[u];
                // FB = conj(eu)*rp0 + rp1 + eu*rp2
                float fbx = eu.x*rp0.x + eu.y*rp0.y + rp1.x + eu.x*rp2.x - eu.y*rp2.y;
                float fby = eu.x*rp0.y - eu.y*rp0.x + rp1.y + eu.x*rp2.y + eu.y*rp2.x;
                float denom = fbx*fbx + fby*fby + sg;
                float scale = 1.0f/(SPECN_F*denom);
                float hx = (fbx+sg)*scale, hy = -fby*scale;
                float2 a = X[j];
                cs[c][u] = make_float2(a.x*hx - a.y*hy, a.x*hy + a.y*hx);
            }
        }
        __syncwarp();
        // ---- inverse column FFT ----
        stageA2(cs[c], As2[c], tws, lane, 32, true);
        __syncwarp();
        for (int q=lane;q<65;q+=32){
            float2 X[4];
            stageC2_quad(As2[c], tws, q, true, X);
            cs[c][q]     = X[0];
            cs[c][q+65]  = X[1];
            cs[c][q+130] = X[2];
            cs[c][q+195] = X[3];
        }
    }
    __syncthreads();
    for (int idx=tid; idx<260*8; idx+=256){
        int r=idx>>3, cc=idx&7;
        if (cc<ncols) base[(size_t)r*SW + cc] = cs[cc][r];
    }
}

// ---------------- inverse row FFT: warp-per-transform, 8 transforms/block --------------
// 128*384 = 49152 transforms, 8 per block -> 6144 blocks.
// spec[ch][u][k] = Y_u[k]; missing k>130 half from SAME row: Y_u[k] = conj(Y_u[260-k]).
__global__ __launch_bounds__(256) void fft_rows_inv_packed(){
    __shared__ float2 zin[8][NP], As[8][NP], tws[NP];
    int tid = threadIdx.x;
    int w = tid >> 5, lane = tid & 31;
    for (int i=tid;i<NP;i+=256) tws[i]=g_tw[i];
    __syncthreads();
    int g = blockIdx.x*8 + w;
    int ch = g/128, pair = g - 128*ch;
    int u0 = 2 + 2*pair, u1 = u0+1;   // padded output rows
    const float2* su0 = g_spec + ((size_t)ch*260 + u0)*SW;
    const float2* su1 = g_spec + ((size_t)ch*260 + u1)*SW;
    float2* zw = zin[w];
    float2* Aw = As[w];
    // z[k] = Y_u0[k] + i*Y_u1[k]
    for (int k=lane;k<=130;k+=32){
        float2 a = su0[k], b = su1[k];
        zw[k] = make_float2(a.x - b.y, a.y + b.x);
    }
    for (int k=131+lane;k<260;k+=32){
        float2 a = su0[260-k], b = su1[260-k];
        zw[k] = make_float2(a.x + b.y, b.x - a.y);
    }
    __syncwarp();
    stageA2(zw, Aw, tws, lane, 32, true);
    __syncwarp();
    for (int q=lane;q<65;q+=32){
        float2 X[4];
        stageC2_quad(Aw, tws, q, true, X);
        zw[q]     = X[0];
        zw[q+65]  = X[1];
        zw[q+130] = X[2];
        zw[q+195] = X[3];
    }
    __syncwarp();
    float* o0 = g_h1 + ((size_t)ch*HH + (u0-2))*WW;
    float* o1 = g_h1 + ((size_t)ch*HH + (u1-2))*WW;
    for (int jj=lane;jj<WW;jj+=32){
        float2 y = zw[jj+2];
        o0[jj] = gelu_f(y.x);
        o1[jj] = gelu_f(y.y);
    }
}

// ---------------- launcher: kernel launches ONLY ----------------
extern "C" void kernel_launch(void* const* d_in, const int* in_sizes, int n_in,
                              void* d_out, int out_size){
    const float* x         = (const float*)d_in[0];
    const float* ln1_w     = (const float*)d_in[1];
    const float* ln1_b     = (const float*)d_in[2];
    const float* w1a       = (const float*)d_in[3];
    const float* b1a       = (const float*)d_in[4];
    const float* conv_w    = (const float*)d_in[5];
    const float* conv_sig  = (const float*)d_in[6];
    const float* w1b       = (const float*)d_in[7];
    const float* b1b       = (const float*)d_in[8];
    const float* ln2_w     = (const float*)d_in[9];
    const float* ln2_b     = (const float*)d_in[10];
    const float* w2a       = (const float*)d_in[11];
    const float* b2a       = (const float*)d_in[12];
    const float* w2b       = (const float*)d_in[13];
    const float* b2b       = (const float*)d_in[14];
    float* out = (float*)d_out;

    init_kernel<<<1, 260>>>(conv_w, conv_sig);

    // branch 1: LN(stats) -> expand+gelu (LN fused) -> converse2d -> gelu -> project + residual
    ln_stats<-1><<<(BB*PIX)/256, 256>>>(x);
    gemm_kernel<CC, C2, 64, 8, 0, 1, -1, -1, 1><<<dim3(PIX/128, C2/64, BB), 128>>>(
        x, w1a, b1a, ln1_w, ln1_b, nullptr, nullptr);

    fft_rows_fwd_packed<<<130*NCH/8, 256>>>();
    fft_cols_fused<<<dim3(17, NCH), 256>>>();
    fft_rows_inv_packed<<<128*NCH/8, 256>>>();

    gemm_kernel<C2, CC, 32, 4, 1, 0, 1, -1, 2><<<dim3(PIX/128, CC/32, BB), 128>>>(
        nullptr, w1b, b1b, nullptr, nullptr, x, nullptr);

    // branch 2: LN(stats) -> expand+gelu (LN fused) -> project + residual
    ln_stats<2><<<(BB*PIX)/256, 256>>>(nullptr);
    gemm_kernel<CC, C2, 64, 8, 0, 1, 2, -1, 1><<<dim3(PIX/128, C2/64, BB), 128>>>(
        nullptr, w2a, b2a, ln2_w, ln2_b, nullptr, nullptr);
    gemm_kernel<C2, CC, 32, 4, 1, 0, 1, 2, -1><<<dim3(PIX/128, CC/32, BB), 128>>>(
        nullptr, w2b, b2b, nullptr, nullptr, nullptr, out);
}

// round 13
// speedup vs baseline: 1.3468x; 1.1561x over previous
#include <cuda_runtime.h>
#include <math.h>

// ---------------- problem constants ----------------
#define BB 2
#define CC 96
#define C2 192
#define HH 256
#define WW 256
#define PIX (HH*WW)          // 65536
#define NP 260               // padded size (256 + 2*2)
#define SW 132               // spectral row stride (131 stored, Hermitian half)
#define NCH (BB*C2)          // 384
#define SPECN_F 67600.0f     // 260*260

// ---------------- scratch (static device globals; no runtime alloc) -------------
__device__ float  g_h1[(size_t)BB*C2*PIX];
__device__ float  g_x2[(size_t)BB*CC*PIX];
__device__ float2 g_spec[(size_t)NCH*260*SW];    // ~105 MB (half-spectrum)
__device__ float  g_mls[(size_t)BB*PIX];         // per-pixel -mu*rstd
__device__ float  g_rs[(size_t)BB*PIX];          // per-pixel rsqrt(var+eps)
__device__ float2 g_tw[NP];                      // e^{-2*pi*i*n/260}
__device__ float  g_w9[C2*9];
__device__ float  g_sig[C2];
__device__ float  g_wpA[C2*CC];                  // w1a * ln1_w (folded)
__device__ float  g_wpB[C2*CC];                  // w2a * ln2_w (folded)
__device__ float  g_sA1[C2], g_sA2[C2];          // S1 = sum W', S2 = sum W*lnb
__device__ float  g_sB1[C2], g_sB2[C2];

// compile-time buffer selector: 1=g_h1, 2=g_x2, -1=external pointer
template<int SEL>
__device__ __forceinline__ float* gbuf(const float* ext){
    if (SEL == 1) return g_h1;
    if (SEL == 2) return g_x2;
    return (float*)ext;
}
template<int SEL>
__device__ __forceinline__ const float* wbuf(const float* ext){
    if (SEL == 0) return g_wpA;
    if (SEL == 1) return g_wpB;
    return ext;
}

__device__ __forceinline__ float gelu_f(float x){
    return 0.5f * x * (1.0f + erff(x * 0.70710678118654752440f));
}

// ---------------- cp.async helpers ----------------
__device__ __forceinline__ void cp_async16(void* dst, const void* src){
    unsigned s = (unsigned)__cvta_generic_to_shared(dst);
    asm volatile("cp.async.cg.shared.global [%0], [%1], 16;" :: "r"(s), "l"(src));
}
__device__ __forceinline__ void cp_commit(){
    asm volatile("cp.async.commit_group;");
}
template<int N>
__device__ __forceinline__ void cp_wait(){
    asm volatile("cp.async.wait_group %0;" :: "n"(N));
}

// ---------------- complex helpers ----------------
__device__ __forceinline__ float2 cmul(float2 a, float2 b){
    return make_float2(a.x*b.x - a.y*b.y, a.x*b.y + a.y*b.x);
}
__device__ __forceinline__ float2 cmac(float2 s, float2 a, float2 t){
    s.x += a.x*t.x - a.y*t.y;
    s.y += a.x*t.y + a.y*t.x;
    return s;
}
__device__ __forceinline__ float2 cadd(float2 a, float2 b){ return make_float2(a.x+b.x, a.y+b.y); }
__device__ __forceinline__ float2 csub(float2 a, float2 b){ return make_float2(a.x-b.x, a.y-b.y); }

// ---------------- init: twiddles + filter params + folded LN weights ----------------
__global__ void init_kernel(const float* __restrict__ conv_w,
                            const float* __restrict__ conv_sigma,
                            const float* __restrict__ w1a,
                            const float* __restrict__ ln1_w,
                            const float* __restrict__ ln1_b,
                            const float* __restrict__ w2a,
                            const float* __restrict__ ln2_w,
                            const float* __restrict__ ln2_b){
    int tid = threadIdx.x;
    if (tid < NP){
        double ang = -2.0 * 3.14159265358979323846 * (double)tid / (double)NP;
        double s, c;
        sincos(ang, &s, &c);
        g_tw[tid] = make_float2((float)c, (float)s);
    }
    for (int ch = tid; ch < C2; ch += blockDim.x){
        float w[9];
        float m = -1e30f;
        #pragma unroll
        for (int i=0;i<9;i++){ w[i] = conv_w[ch*9+i]; m = fmaxf(m, w[i]); }
        float ssum = 0.f;
        #pragma unroll
        for (int i=0;i<9;i++){ w[i] = expf(w[i]-m); ssum += w[i]; }
        float inv = 1.f/ssum;
        #pragma unroll
        for (int i=0;i<9;i++) g_w9[ch*9+i] = w[i]*inv;
        float sp = conv_sigma[ch];
        g_sig[ch] = 1.f/(1.f + expf(9.f - sp)) + 1e-5f;
        // folded LN weights for the two expansion GEMMs
        float s1a=0.f, s2a=0.f, s1b=0.f, s2b=0.f;
        for (int c=0;c<CC;c++){
            float wa = w1a[ch*CC+c];
            float wpa = wa*ln1_w[c];
            g_wpA[ch*CC+c] = wpa;
            s1a += wpa; s2a += wa*ln1_b[c];
            float wb = w2a[ch*CC+c];
            float wpb = wb*ln2_w[c];
            g_wpB[ch*CC+c] = wpb;
            s1b += wpb; s2b += wb*ln2_b[c];
        }
        g_sA1[ch]=s1a; g_sA2[ch]=s2a;
        g_sB1[ch]=s1b; g_sB2[ch]=s2b;
    }
}

// ---------------- LN statistics: per-pixel -mu*rstd & rstd over channels -------------
template<int XSEL>
__global__ void ln_stats(const float* __restrict__ xext){
    const float* x = gbuf<XSEL>(xext);
    int pi = blockIdx.x*blockDim.x + threadIdx.x;
    if (pi >= BB*PIX) return;
    int bb = pi >> 16;
    int p  = pi & (PIX-1);
    const float* xb = x + (size_t)bb*CC*PIX + p;
    float s=0.f, s2=0.f;
    #pragma unroll 4
    for (int c=0;c<CC;c++){ float v = xb[(size_t)c*PIX]; s += v; s2 += v*v; }
    float mu  = s * (1.f/CC);
    float var = s2 * (1.f/CC) - mu*mu;
    float rs  = rsqrtf(var + 1e-5f);
    g_rs[pi]  = rs;
    g_mls[pi] = -mu*rs;
}

// ---------------- 1x1 conv as SGEMM: W-slab resident, cp.async double-buffered X -----
// MODE 0 (expansion, LN folded): out = gelu(rs[p]*acc + mls[p]*S1[o] + S2[o] + bias[o])
// MODE 1 (projection):           out = acc + bias[o] + res
template<int CIN, int COUT, int BN, int TN, int MODE, int WSEL, int SSEL,
         int XSEL, int RSEL, int OSEL>
__global__ __launch_bounds__(128) void gemm_kernel(
                            const float* __restrict__ Xext,
                            const float* __restrict__ Wext,
                            const float* __restrict__ bias,
                            const float* __restrict__ Rext,
                            float* __restrict__ Oext){
    const float* X   = gbuf<XSEL>(Xext);
    const float* res = gbuf<RSEL>(Rext);
    float*       out = gbuf<OSEL>(Oext);
    const float* Wsrc = wbuf<WSEL>(Wext);
    const int BM=128, BK=16, NCHK=CIN/BK, WP=BN+4;
    __shared__ __align__(16) float Xs[2][BK][BM];
    __shared__ __align__(16) float Wall[CIN][WP];
    int bb = blockIdx.z;
    int p0 = blockIdx.x*BM;
    int o0 = blockIdx.y*BN;
    int tid = threadIdx.x;       // 128
    int tx = tid & 15;           // pixel group
    int ty = tid >> 4;           // output group (TN outs)
    float acc[TN][8];
    #pragma unroll
    for (int j=0;j<TN;j++)
        #pragma unroll
        for (int i=0;i<8;i++) acc[j][i]=0.f;

    const float* Xb = X + (size_t)bb*CIN*PIX + p0;

    // prefetch chunk 0 (cp.async), then stage the whole W slab
    #pragma unroll
    for (int ii=0; ii<4; ii++){
        int idx = tid + 128*ii;
        int k = idx >> 5, c4 = idx & 31;
        cp_async16(&Xs[0][k][c4*4], Xb + (size_t)k*PIX + c4*4);
    }
    cp_commit();
    for (int idx=tid; idx<CIN*BN; idx+=128){
        int o = idx / CIN, k = idx - o*CIN;
        Wall[k][o] = Wsrc[(size_t)(o0+o)*CIN + k];
    }

    for (int c=0; c<NCHK; c++){
        int cur = c & 1;
        if (c+1 < NCHK){
            const float* Xc = Xb + (size_t)(c+1)*BK*PIX;
            #pragma unroll
            for (int ii=0; ii<4; ii++){
                int idx = tid + 128*ii;
                int k = idx >> 5, c4 = idx & 31;
                cp_async16(&Xs[cur^1][k][c4*4], Xc + (size_t)k*PIX + c4*4);
            }
            cp_commit();
            cp_wait<1>();
        } else {
            cp_wait<0>();
        }
        __syncthreads();
        #pragma unroll
        for (int k=0;k<BK;k++){
            int kg = c*BK + k;
            float4 x0 = *(const float4*)&Xs[cur][k][tx*4];        // conflict-free
            float4 x1 = *(const float4*)&Xs[cur][k][64 + tx*4];   // conflict-free
            float xa[8] = {x0.x,x0.y,x0.z,x0.w,x1.x,x1.y,x1.z,x1.w};
            float wa[TN];
            #pragma unroll
            for (int j4=0;j4<TN;j4+=4){
                float4 wv = *(const float4*)&Wall[kg][ty*TN + j4];
                wa[j4]=wv.x; wa[j4+1]=wv.y; wa[j4+2]=wv.z; wa[j4+3]=wv.w;
            }
            #pragma unroll
            for (int j=0;j<TN;j++)
                #pragma unroll
                for (int i=0;i<8;i++)
                    acc[j][i] += xa[i]*wa[j];
        }
        __syncthreads();
    }

    float rsv[8], mlv[8];
    if (MODE==0){
        size_t sb = (size_t)bb*PIX + p0;
        float4 r0 = *(const float4*)(g_rs  + sb + tx*4);
        float4 r1 = *(const float4*)(g_rs  + sb + 64 + tx*4);
        float4 m0 = *(const float4*)(g_mls + sb + tx*4);
        float4 m1 = *(const float4*)(g_mls + sb + 64 + tx*4);
        rsv[0]=r0.x; rsv[1]=r0.y; rsv[2]=r0.z; rsv[3]=r0.w;
        rsv[4]=r1.x; rsv[5]=r1.y; rsv[6]=r1.z; rsv[7]=r1.w;
        mlv[0]=m0.x; mlv[1]=m0.y; mlv[2]=m0.z; mlv[3]=m0.w;
        mlv[4]=m1.x; mlv[5]=m1.y; mlv[6]=m1.z; mlv[7]=m1.w;
    }
    const float* S1 = (SSEL==0) ? g_sA1 : g_sB1;
    const float* S2 = (SSEL==0) ? g_sA2 : g_sB2;
    #pragma unroll
    for (int j=0;j<TN;j++){
        int o = o0 + ty*TN + j;
        float bj = bias[o];
        size_t ob = ((size_t)(bb*COUT + o))*PIX + p0;
        size_t oidx0 = ob + tx*4;
        size_t oidx1 = ob + 64 + tx*4;
        float v[8];
        if (MODE==0){
            float s1 = S1[o], s2 = S2[o];
            #pragma unroll
            for (int i=0;i<8;i++)
                v[i] = gelu_f(rsv[i]*acc[j][i] + mlv[i]*s1 + s2 + bj);
        } else {
            float4 r0 = *(const float4*)(res + oidx0);
            float4 r1 = *(const float4*)(res + oidx1);
            v[0]=acc[j][0]+bj+r0.x; v[1]=acc[j][1]+bj+r0.y;
            v[2]=acc[j][2]+bj+r0.z; v[3]=acc[j][3]+bj+r0.w;
            v[4]=acc[j][4]+bj+r1.x; v[5]=acc[j][5]+bj+r1.y;
            v[6]=acc[j][6]+bj+r1.z; v[7]=acc[j][7]+bj+r1.w;
        }
        *(float4*)(out + oidx0) = make_float4(v[0],v[1],v[2],v[3]);
        *(float4*)(out + oidx1) = make_float4(v[4],v[5],v[6],v[7]);
    }
}

// ---------------- FFT core: 260 = 20 x 13 (13-pt DFTs then radix-4 20-pt stage) --------
__device__ __forceinline__ void stageA2(const float2* __restrict__ z,
                                        float2* __restrict__ A2,
                                        const float2* __restrict__ tws,
                                        int lane, int stride, bool inv){
    for (int o=lane;o<NP;o+=stride){
        int b = o/13, k2 = o - 13*b;
        float2 t1 = tws[20*k2];
        if (inv) t1.y = -t1.y;
        float2 t = make_float2(1.f,0.f);
        float2 s = make_float2(0.f,0.f);
        #pragma unroll
        for (int a=0;a<13;a++){
            float2 v = z[20*a + b];
            s = cmac(s, v, t);
            t = cmul(t, t1);
        }
        A2[o] = s;   // o == 13b + k2
    }
}

// compute outputs X[q + 65j], j=0..3
__device__ __forceinline__ void stageC2_quad(const float2* __restrict__ A2,
                                             const float2* __restrict__ tws,
                                             int q, bool inv, float2 X[4]){
    int k2 = q % 13;
    float2 t1 = tws[q]; if (inv) t1.y = -t1.y;
    float2 t2 = cmul(t1,t1);
    float2 u  = cmul(t2,t2);     // t1^4
    float2 S0=make_float2(0,0), S1=make_float2(0,0), S2=make_float2(0,0), S3=make_float2(0,0);
    float2 t = make_float2(1.f,0.f);
    #pragma unroll
    for (int m=0;m<5;m++){
        const float2* base = A2 + (4*m)*13 + k2;
        float2 v0 = base[0], v1 = base[13], v2 = base[26], v3 = base[39];
        S0 = cmac(S0, v0, t);
        S1 = cmac(S1, v1, t);
        S2 = cmac(S2, v2, t);
        S3 = cmac(S3, v3, t);
        t = cmul(t, u);
    }
    float2 T1 = cmul(t1, S1);
    float2 T2 = cmul(t2, S2);
    float2 t3 = cmul(t2, t1);
    float2 T3 = cmul(t3, S3);
    float2 E0 = cadd(S0, T2), E1 = csub(S0, T2);
    float2 O0 = cadd(T1, T3), O1 = csub(T1, T3);
    X[0] = cadd(E0, O0);
    X[2] = csub(E0, O0);
    if (!inv){   // omega = -i
        X[1] = make_float2(E1.x + O1.y, E1.y - O1.x);
        X[3] = make_float2(E1.x - O1.y, E1.y + O1.x);
    } else {     // omega = +i
        X[1] = make_float2(E1.x - O1.y, E1.y + O1.x);
        X[3] = make_float2(E1.x + O1.y, E1.y - O1.x);
    }
}

// ---------------- forward row FFT: warp-per-transform, 8 transforms/block --------------
// 130*384 = 49920 row-pair transforms, 8 per block -> 6240 blocks.
__global__ __launch_bounds__(256) void fft_rows_fwd_packed(){
    __shared__ float2 xin[8][NP], As[8][NP], tws[NP];
    int tid = threadIdx.x;
    int w = tid >> 5, lane = tid & 31;
    for (int i=tid;i<NP;i+=256) tws[i]=g_tw[i];
    __syncthreads();
    int g = blockIdx.x*8 + w;
    int ch = g/130, pair = g - 130*ch;
    int r0 = 2*pair, r1 = r0+1;
    int s0 = min(max(r0-2,0),HH-1), s1 = min(max(r1-2,0),HH-1);
    const float* p0r = g_h1 + ((size_t)ch*HH + s0)*WW;
    const float* p1r = g_h1 + ((size_t)ch*HH + s1)*WW;
    float2* xw = xin[w];
    float2* Aw = As[w];
    for (int i=lane;i<NP;i+=32){
        int sc = min(max(i-2,0),WW-1);
        xw[i] = make_float2(p0r[sc], p1r[sc]);
    }
    __syncwarp();
    stageA2(xw, Aw, tws, lane, 32, false);
    __syncwarp();
    for (int q=lane;q<65;q+=32){
        float2 X[4];
        stageC2_quad(Aw, tws, q, false, X);
        xw[q]      = X[0];
        xw[q+65]   = X[1];
        xw[q+130]  = X[2];
        xw[q+195]  = X[3];
    }
    __syncwarp();
    float2* o0 = g_spec + ((size_t)ch*260 + r0)*SW;
    float2* o1 = g_spec + ((size_t)ch*260 + r1)*SW;
    for (int k=lane;k<=130;k+=32){
        float2 Zk = xw[k];
        float2 Zm = xw[(260-k)%260];
        // unpack: A=(Z[k]+conj(Z[-k]))/2, B=(Z[k]-conj(Z[-k]))/(2i)
        o0[k] = make_float2(0.5f*(Zk.x+Zm.x), 0.5f*(Zk.y-Zm.y));
        o1[k] = make_float2(0.5f*(Zk.y+Zm.y), 0.5f*(Zm.x-Zk.x));
    }
}

// ---------------- fused column pass: fwd col FFT + filter + inv col FFT ----------------
__global__ void fft_cols_fused(){
    int k0 = blockIdx.x*8;   // 17 blocks cover 131 columns
    int ch = blockIdx.y;
    __shared__ float2 cs[8][NP];
    __shared__ float2 As2[8][NP];
    __shared__ float2 tws[NP];
    __shared__ float ws[10];
    int tid = threadIdx.x;   // 256
    for (int i=tid;i<NP;i+=256) tws[i]=g_tw[i];
    {
        int c2ch = ch % C2;
        if (tid<9) ws[tid]=g_w9[c2ch*9+tid];
        if (tid==9) ws[9]=g_sig[c2ch];
    }
    float2* base = g_spec + (size_t)ch*260*SW + k0;
    int ncols = 131 - k0; if (ncols>8) ncols=8;
    __syncthreads();
    for (int idx=tid; idx<260*8; idx+=256){
        int r=idx>>3, c=idx&7;
        if (c<ncols) cs[c][r] = base[(size_t)r*SW + c];
    }
    __syncthreads();
    int c = tid>>5, lane = tid&31;
    if (c < ncols){
        // ---- forward column FFT ----
        stageA2(cs[c], As2[c], tws, lane, 32, false);
        __syncwarp();
        int k = k0 + c;
        float2 ev = tws[k];
        float2 rp0 = make_float2(ws[0]*ev.x + ws[1] + ws[2]*ev.x, -ws[0]*ev.y + ws[2]*ev.y);
        float2 rp1 = make_float2(ws[3]*ev.x + ws[4] + ws[5]*ev.x, -ws[3]*ev.y + ws[5]*ev.y);
        float2 rp2 = make_float2(ws[6]*ev.x + ws[7] + ws[8]*ev.x, -ws[6]*ev.y + ws[8]*ev.y);
        float sg = ws[9];
        for (int q=lane;q<65;q+=32){
            float2 X[4];
            stageC2_quad(As2[c], tws, q, false, X);
            #pragma unroll
            for (int j=0;j<4;j++){
                int u = q + 65*j;
                float2 eu = tws[u];
                // FB = conj(eu)*rp0 + rp1 + eu*rp2
                float fbx = eu.x*rp0.x + eu.y*rp0.y + rp1.x + eu.x*rp2.x - eu.y*rp2.y;
                float fby = eu.x*rp0.y - eu.y*rp0.x + rp1.y + eu.x*rp2.y + eu.y*rp2.x;
                float denom = fbx*fbx + fby*fby + sg;
                float scale = 1.0f/(SPECN_F*denom);
                float hx = (fbx+sg)*scale, hy = -fby*scale;
                float2 a = X[j];
                cs[c][u] = make_float2(a.x*hx - a.y*hy, a.x*hy + a.y*hx);
            }
        }
        __syncwarp();
        // ---- inverse column FFT ----
        stageA2(cs[c], As2[c], tws, lane, 32, true);
        __syncwarp();
        for (int q=lane;q<65;q+=32){
            float2 X[4];
            stageC2_quad(As2[c], tws, q, true, X);
            cs[c][q]     = X[0];
            cs[c][q+65]  = X[1];
            cs[c][q+130] = X[2];
            cs[c][q+195] = X[3];
        }
    }
    __syncthreads();
    for (int idx=tid; idx<260*8; idx+=256){
        int r=idx>>3, cc=idx&7;
        if (cc<ncols) base[(size_t)r*SW + cc] = cs[cc][r];
    }
}

// ---------------- inverse row FFT: warp-per-transform, 8 transforms/block --------------
// 128*384 = 49152 transforms, 8 per block -> 6144 blocks.
// spec[ch][u][k] = Y_u[k]; missing k>130 half from SAME row: Y_u[k] = conj(Y_u[260-k]).
__global__ __launch_bounds__(256) void fft_rows_inv_packed(){
    __shared__ float2 zin[8][NP], As[8][NP], tws[NP];
    int tid = threadIdx.x;
    int w = tid >> 5, lane = tid & 31;
    for (int i=tid;i<NP;i+=256) tws[i]=g_tw[i];
    __syncthreads();
    int g = blockIdx.x*8 + w;
    int ch = g/128, pair = g - 128*ch;
    int u0 = 2 + 2*pair, u1 = u0+1;   // padded output rows
    const float2* su0 = g_spec + ((size_t)ch*260 + u0)*SW;
    const float2* su1 = g_spec + ((size_t)ch*260 + u1)*SW;
    float2* zw = zin[w];
    float2* Aw = As[w];
    // z[k] = Y_u0[k] + i*Y_u1[k]
    for (int k=lane;k<=130;k+=32){
        float2 a = su0[k], b = su1[k];
        zw[k] = make_float2(a.x - b.y, a.y + b.x);
    }
    for (int k=131+lane;k<260;k+=32){
        float2 a = su0[260-k], b = su1[260-k];
        zw[k] = make_float2(a.x + b.y, b.x - a.y);
    }
    __syncwarp();
    stageA2(zw, Aw, tws, lane, 32, true);
    __syncwarp();
    for (int q=lane;q<65;q+=32){
        float2 X[4];
        stageC2_quad(Aw, tws, q, true, X);
        zw[q]     = X[0];
        zw[q+65]  = X[1];
        zw[q+130] = X[2];
        zw[q+195] = X[3];
    }
    __syncwarp();
    float* o0 = g_h1 + ((size_t)ch*HH + (u0-2))*WW;
    float* o1 = g_h1 + ((size_t)ch*HH + (u1-2))*WW;
    for (int jj=lane;jj<WW;jj+=32){
        float2 y = zw[jj+2];
        o0[jj] = gelu_f(y.x);
        o1[jj] = gelu_f(y.y);
    }
}

// ---------------- launcher: kernel launches ONLY ----------------
extern "C" void kernel_launch(void* const* d_in, const int* in_sizes, int n_in,
                              void* d_out, int out_size){
    const float* x         = (const float*)d_in[0];
    const float* ln1_w     = (const float*)d_in[1];
    const float* ln1_b     = (const float*)d_in[2];
    const float* w1a       = (const float*)d_in[3];
    const float* b1a       = (const float*)d_in[4];
    const float* conv_w    = (const float*)d_in[5];
    const float* conv_sig  = (const float*)d_in[6];
    const float* w1b       = (const float*)d_in[7];
    const float* b1b       = (const float*)d_in[8];
    const float* ln2_w     = (const float*)d_in[9];
    const float* ln2_b     = (const float*)d_in[10];
    const float* w2a       = (const float*)d_in[11];
    const float* b2a       = (const float*)d_in[12];
    const float* w2b       = (const float*)d_in[13];
    const float* b2b       = (const float*)d_in[14];
    float* out = (float*)d_out;

    init_kernel<<<1, 260>>>(conv_w, conv_sig, w1a, ln1_w, ln1_b, w2a, ln2_w, ln2_b);

    // branch 1: LN(stats) -> expand+gelu (LN folded into W/epilogue) -> converse2d -> gelu
    //           -> project + residual
    ln_stats<-1><<<(BB*PIX)/256, 256>>>(x);
    gemm_kernel<CC, C2, 64, 8, 0, 0, 0, -1, -1, 1><<<dim3(PIX/128, C2/64, BB), 128>>>(
        x, nullptr, b1a, nullptr, nullptr);

    fft_rows_fwd_packed<<<130*NCH/8, 256>>>();
    fft_cols_fused<<<dim3(17, NCH), 256>>>();
    fft_rows_inv_packed<<<128*NCH/8, 256>>>();

    gemm_kernel<C2, CC, 32, 4, 1, -1, 0, 1, -1, 2><<<dim3(PIX/128, CC/32, BB), 128>>>(
        nullptr, w1b, b1b, x, nullptr);

    // branch 2: LN(stats) -> expand+gelu (LN folded) -> project + residual
    ln_stats<2><<<(BB*PIX)/256, 256>>>(nullptr);
    gemm_kernel<CC, C2, 64, 8, 0, 1, 1, 2, -1, 1><<<dim3(PIX/128, C2/64, BB), 128>>>(
        nullptr, nullptr, b2a, nullptr, nullptr);
    gemm_kernel<C2, CC, 32, 4, 1, -1, 0, 1, 2, -1><<<dim3(PIX/128, CC/32, BB), 128>>>(
        nullptr, w2b, b2b, nullptr, out);
}

// round 14
// speedup vs baseline: 1.3964x; 1.0368x over previous
#include <cuda_runtime.h>
#include <math.h>

// ---------------- problem constants ----------------
#define BB 2
#define CC 96
#define C2 192
#define HH 256
#define WW 256
#define PIX (HH*WW)          // 65536
#define NP 260               // padded size (256 + 2*2)
#define SW 132               // spectral row stride (131 stored, Hermitian half)
#define NCH (BB*C2)          // 384
#define SPECN_F 67600.0f     // 260*260

// ---------------- scratch (static device globals; no runtime alloc) -------------
__device__ float  g_h1[(size_t)BB*C2*PIX];
__device__ float  g_x2[(size_t)BB*CC*PIX];
__device__ float2 g_spec[(size_t)NCH*260*SW];    // ~105 MB (half-spectrum)
__device__ float  g_mls[(size_t)BB*PIX];         // per-pixel -mu*rstd
__device__ float  g_rs[(size_t)BB*PIX];          // per-pixel rsqrt(var+eps)
__device__ float2 g_tw[NP];                      // e^{-2*pi*i*n/260}
__device__ float  g_w9[C2*9];
__device__ float  g_sig[C2];
__device__ float  g_wpA[C2*CC];                  // w1a * ln1_w (folded)
__device__ float  g_wpB[C2*CC];                  // w2a * ln2_w (folded)
__device__ float  g_sA1[C2], g_sA2[C2];          // S1 = sum W', S2 = sum W*lnb
__device__ float  g_sB1[C2], g_sB2[C2];

// compile-time buffer selector: 1=g_h1, 2=g_x2, -1=external pointer
template<int SEL>
__device__ __forceinline__ float* gbuf(const float* ext){
    if (SEL == 1) return g_h1;
    if (SEL == 2) return g_x2;
    return (float*)ext;
}
template<int SEL>
__device__ __forceinline__ const float* wbuf(const float* ext){
    if (SEL == 0) return g_wpA;
    if (SEL == 1) return g_wpB;
    return ext;
}

__device__ __forceinline__ float gelu_f(float x){
    return 0.5f * x * (1.0f + erff(x * 0.70710678118654752440f));
}

// ---------------- packed f32x2 FMA (Blackwell dual-FMA pipe) ----------------
__device__ __forceinline__ void fma_f32x2(unsigned long long& d,
                                          unsigned long long a,
                                          unsigned long long b){
    asm("fma.rn.f32x2 %0, %1, %2, %0;" : "+l"(d) : "l"(a), "l"(b));
}
__device__ __forceinline__ unsigned long long pack_dup(float x){
    unsigned long long r;
    asm("mov.b64 %0, {%1, %1};" : "=l"(r) : "f"(x));
    return r;
}
__device__ __forceinline__ void unpack2(unsigned long long v, float& lo, float& hi){
    asm("mov.b64 {%0, %1}, %2;" : "=f"(lo), "=f"(hi) : "l"(v));
}

// ---------------- cp.async helpers ----------------
__device__ __forceinline__ void cp_async16(void* dst, const void* src){
    unsigned s = (unsigned)__cvta_generic_to_shared(dst);
    asm volatile("cp.async.cg.shared.global [%0], [%1], 16;" :: "r"(s), "l"(src));
}
__device__ __forceinline__ void cp_commit(){
    asm volatile("cp.async.commit_group;");
}
template<int N>
__device__ __forceinline__ void cp_wait(){
    asm volatile("cp.async.wait_group %0;" :: "n"(N));
}

// ---------------- complex helpers ----------------
__device__ __forceinline__ float2 cmul(float2 a, float2 b){
    return make_float2(a.x*b.x - a.y*b.y, a.x*b.y + a.y*b.x);
}
__device__ __forceinline__ float2 cmac(float2 s, float2 a, float2 t){
    s.x += a.x*t.x - a.y*t.y;
    s.y += a.x*t.y + a.y*t.x;
    return s;
}
__device__ __forceinline__ float2 cadd(float2 a, float2 b){ return make_float2(a.x+b.x, a.y+b.y); }
__device__ __forceinline__ float2 csub(float2 a, float2 b){ return make_float2(a.x-b.x, a.y-b.y); }

// ---------------- init: twiddles + filter params + folded LN weights ----------------
__global__ void init_kernel(const float* __restrict__ conv_w,
                            const float* __restrict__ conv_sigma,
                            const float* __restrict__ w1a,
                            const float* __restrict__ ln1_w,
                            const float* __restrict__ ln1_b,
                            const float* __restrict__ w2a,
                            const float* __restrict__ ln2_w,
                            const float* __restrict__ ln2_b){
    int tid = threadIdx.x;
    if (tid < NP){
        double ang = -2.0 * 3.14159265358979323846 * (double)tid / (double)NP;
        double s, c;
        sincos(ang, &s, &c);
        g_tw[tid] = make_float2((float)c, (float)s);
    }
    for (int ch = tid; ch < C2; ch += blockDim.x){
        float w[9];
        float m = -1e30f;
        #pragma unroll
        for (int i=0;i<9;i++){ w[i] = conv_w[ch*9+i]; m = fmaxf(m, w[i]); }
        float ssum = 0.f;
        #pragma unroll
        for (int i=0;i<9;i++){ w[i] = expf(w[i]-m); ssum += w[i]; }
        float inv = 1.f/ssum;
        #pragma unroll
        for (int i=0;i<9;i++) g_w9[ch*9+i] = w[i]*inv;
        float sp = conv_sigma[ch];
        g_sig[ch] = 1.f/(1.f + expf(9.f - sp)) + 1e-5f;
        // folded LN weights for the two expansion GEMMs
        float s1a=0.f, s2a=0.f, s1b=0.f, s2b=0.f;
        for (int c=0;c<CC;c++){
            float wa = w1a[ch*CC+c];
            float wpa = wa*ln1_w[c];
            g_wpA[ch*CC+c] = wpa;
            s1a += wpa; s2a += wa*ln1_b[c];
            float wb = w2a[ch*CC+c];
            float wpb = wb*ln2_w[c];
            g_wpB[ch*CC+c] = wpb;
            s1b += wpb; s2b += wb*ln2_b[c];
        }
        g_sA1[ch]=s1a; g_sA2[ch]=s2a;
        g_sB1[ch]=s1b; g_sB2[ch]=s2b;
    }
}

// ---------------- LN statistics: per-pixel -mu*rstd & rstd over channels -------------
template<int XSEL>
__global__ void ln_stats(const float* __restrict__ xext){
    const float* x = gbuf<XSEL>(xext);
    int pi = blockIdx.x*blockDim.x + threadIdx.x;
    if (pi >= BB*PIX) return;
    int bb = pi >> 16;
    int p  = pi & (PIX-1);
    const float* xb = x + (size_t)bb*CC*PIX + p;
    float s=0.f, s2=0.f;
    #pragma unroll 4
    for (int c=0;c<CC;c++){ float v = xb[(size_t)c*PIX]; s += v; s2 += v*v; }
    float mu  = s * (1.f/CC);
    float var = s2 * (1.f/CC) - mu*mu;
    float rs  = rsqrtf(var + 1e-5f);
    g_rs[pi]  = rs;
    g_mls[pi] = -mu*rs;
}

// ---------------- 1x1 conv as SGEMM: FFMA2 inner loop, cp.async double-buffered X ----
// MODE 0 (expansion, LN folded): out = gelu(rs[p]*acc + mls[p]*S1[o] + S2[o] + bias[o])
// MODE 1 (projection):           out = acc + bias[o] + res
// Accumulators packed over OUTPUT pairs: accp[jp][i] = (acc[2jp][i], acc[2jp+1][i]),
// so W pairs load directly from shared as 64-bit and X needs one dup-pack per pixel.
template<int CIN, int COUT, int BN, int TN, int MODE, int WSEL, int SSEL,
         int XSEL, int RSEL, int OSEL>
__global__ __launch_bounds__(128) void gemm_kernel(
                            const float* __restrict__ Xext,
                            const float* __restrict__ Wext,
                            const float* __restrict__ bias,
                            const float* __restrict__ Rext,
                            float* __restrict__ Oext){
    const float* X   = gbuf<XSEL>(Xext);
    const float* res = gbuf<RSEL>(Rext);
    float*       out = gbuf<OSEL>(Oext);
    const float* Wsrc = wbuf<WSEL>(Wext);
    const int BM=128, BK=16, NCHK=CIN/BK, WP=BN+4, J2=TN/2;
    __shared__ __align__(16) float Xs[2][BK][BM];
    __shared__ __align__(16) float Wall[CIN][WP];
    int bb = blockIdx.z;
    int p0 = blockIdx.x*BM;
    int o0 = blockIdx.y*BN;
    int tid = threadIdx.x;       // 128
    int tx = tid & 15;           // pixel group
    int ty = tid >> 4;           // output group (TN outs)
    unsigned long long accp[J2][8];
    #pragma unroll
    for (int jp=0;jp<J2;jp++)
        #pragma unroll
        for (int i=0;i<8;i++) accp[jp][i]=0ULL;

    const float* Xb = X + (size_t)bb*CIN*PIX + p0;

    // prefetch chunk 0 (cp.async), then stage the whole W slab
    #pragma unroll
    for (int ii=0; ii<4; ii++){
        int idx = tid + 128*ii;
        int k = idx >> 5, c4 = idx & 31;
        cp_async16(&Xs[0][k][c4*4], Xb + (size_t)k*PIX + c4*4);
    }
    cp_commit();
    for (int idx=tid; idx<CIN*BN; idx+=128){
        int o = idx / CIN, k = idx - o*CIN;
        Wall[k][o] = Wsrc[(size_t)(o0+o)*CIN + k];
    }

    for (int c=0; c<NCHK; c++){
        int cur = c & 1;
        if (c+1 < NCHK){
            const float* Xc = Xb + (size_t)(c+1)*BK*PIX;
            #pragma unroll
            for (int ii=0; ii<4; ii++){
                int idx = tid + 128*ii;
                int k = idx >> 5, c4 = idx & 31;
                cp_async16(&Xs[cur^1][k][c4*4], Xc + (size_t)k*PIX + c4*4);
            }
            cp_commit();
            cp_wait<1>();
        } else {
            cp_wait<0>();
        }
        __syncthreads();
        #pragma unroll
        for (int k=0;k<BK;k++){
            int kg = c*BK + k;
            float4 x0 = *(const float4*)&Xs[cur][k][tx*4];        // conflict-free
            float4 x1 = *(const float4*)&Xs[cur][k][64 + tx*4];   // conflict-free
            unsigned long long xp[8];
            xp[0]=pack_dup(x0.x); xp[1]=pack_dup(x0.y);
            xp[2]=pack_dup(x0.z); xp[3]=pack_dup(x0.w);
            xp[4]=pack_dup(x1.x); xp[5]=pack_dup(x1.y);
            xp[6]=pack_dup(x1.z); xp[7]=pack_dup(x1.w);
            // W pairs: TN consecutive floats at 16B-aligned base -> J2 64-bit reads
            unsigned long long wp[J2];
            #pragma unroll
            for (int jp=0;jp<J2;jp++)
                wp[jp] = *(const unsigned long long*)&Wall[kg][ty*TN + 2*jp];
            #pragma unroll
            for (int jp=0;jp<J2;jp++)
                #pragma unroll
                for (int i=0;i<8;i++)
                    fma_f32x2(accp[jp][i], xp[i], wp[jp]);
        }
        __syncthreads();
    }

    // unpack accumulators
    float acc[TN][8];
    #pragma unroll
    for (int jp=0;jp<J2;jp++)
        #pragma unroll
        for (int i=0;i<8;i++)
            unpack2(accp[jp][i], acc[2*jp][i], acc[2*jp+1][i]);

    float rsv[8], mlv[8];
    if (MODE==0){
        size_t sb = (size_t)bb*PIX + p0;
        float4 r0 = *(const float4*)(g_rs  + sb + tx*4);
        float4 r1 = *(const float4*)(g_rs  + sb + 64 + tx*4);
        float4 m0 = *(const float4*)(g_mls + sb + tx*4);
        float4 m1 = *(const float4*)(g_mls + sb + 64 + tx*4);
        rsv[0]=r0.x; rsv[1]=r0.y; rsv[2]=r0.z; rsv[3]=r0.w;
        rsv[4]=r1.x; rsv[5]=r1.y; rsv[6]=r1.z; rsv[7]=r1.w;
        mlv[0]=m0.x; mlv[1]=m0.y; mlv[2]=m0.z; mlv[3]=m0.w;
        mlv[4]=m1.x; mlv[5]=m1.y; mlv[6]=m1.z; mlv[7]=m1.w;
    }
    const float* S1 = (SSEL==0) ? g_sA1 : g_sB1;
    const float* S2 = (SSEL==0) ? g_sA2 : g_sB2;
    #pragma unroll
    for (int j=0;j<TN;j++){
        int o = o0 + ty*TN + j;
        float bj = bias[o];
        size_t ob = ((size_t)(bb*COUT + o))*PIX + p0;
        size_t oidx0 = ob + tx*4;
        size_t oidx1 = ob + 64 + tx*4;
        float v[8];
        if (MODE==0){
            float s1 = S1[o], s2 = S2[o];
            #pragma unroll
            for (int i=0;i<8;i++)
                v[i] = gelu_f(rsv[i]*acc[j][i] + mlv[i]*s1 + s2 + bj);
        } else {
            float4 r0 = *(const float4*)(res + oidx0);
            float4 r1 = *(const float4*)(res + oidx1);
            v[0]=acc[j][0]+bj+r0.x; v[1]=acc[j][1]+bj+r0.y;
            v[2]=acc[j][2]+bj+r0.z; v[3]=acc[j][3]+bj+r0.w;
            v[4]=acc[j][4]+bj+r1.x; v[5]=acc[j][5]+bj+r1.y;
            v[6]=acc[j][6]+bj+r1.z; v[7]=acc[j][7]+bj+r1.w;
        }
        *(float4*)(out + oidx0) = make_float4(v[0],v[1],v[2],v[3]);
        *(float4*)(out + oidx1) = make_float4(v[4],v[5],v[6],v[7]);
    }
}

// ---------------- FFT core: 260 = 20 x 13 (13-pt DFTs then radix-4 20-pt stage) --------
__device__ __forceinline__ void stageA2(const float2* __restrict__ z,
                                        float2* __restrict__ A2,
                                        const float2* __restrict__ tws,
                                        int lane, int stride, bool inv){
    for (int o=lane;o<NP;o+=stride){
        int b = o/13, k2 = o - 13*b;
        float2 t1 = tws[20*k2];
        if (inv) t1.y = -t1.y;
        float2 t = make_float2(1.f,0.f);
        float2 s = make_float2(0.f,0.f);
        #pragma unroll
        for (int a=0;a<13;a++){
            float2 v = z[20*a + b];
            s = cmac(s, v, t);
            t = cmul(t, t1);
        }
        A2[o] = s;   // o == 13b + k2
    }
}

// compute outputs X[q + 65j], j=0..3
__device__ __forceinline__ void stageC2_quad(const float2* __restrict__ A2,
                                             const float2* __restrict__ tws,
                                             int q, bool inv, float2 X[4]){
    int k2 = q % 13;
    float2 t1 = tws[q]; if (inv) t1.y = -t1.y;
    float2 t2 = cmul(t1,t1);
    float2 u  = cmul(t2,t2);     // t1^4
    float2 S0=make_float2(0,0), S1=make_float2(0,0), S2=make_float2(0,0), S3=make_float2(0,0);
    float2 t = make_float2(1.f,0.f);
    #pragma unroll
    for (int m=0;m<5;m++){
        const float2* base = A2 + (4*m)*13 + k2;
        float2 v0 = base[0], v1 = base[13], v2 = base[26], v3 = base[39];
        S0 = cmac(S0, v0, t);
        S1 = cmac(S1, v1, t);
        S2 = cmac(S2, v2, t);
        S3 = cmac(S3, v3, t);
        t = cmul(t, u);
    }
    float2 T1 = cmul(t1, S1);
    float2 T2 = cmul(t2, S2);
    float2 t3 = cmul(t2, t1);
    float2 T3 = cmul(t3, S3);
    float2 E0 = cadd(S0, T2), E1 = csub(S0, T2);
    float2 O0 = cadd(T1, T3), O1 = csub(T1, T3);
    X[0] = cadd(E0, O0);
    X[2] = csub(E0, O0);
    if (!inv){   // omega = -i
        X[1] = make_float2(E1.x + O1.y, E1.y - O1.x);
        X[3] = make_float2(E1.x - O1.y, E1.y + O1.x);
    } else {     // omega = +i
        X[1] = make_float2(E1.x - O1.y, E1.y + O1.x);
        X[3] = make_float2(E1.x + O1.y, E1.y - O1.x);
    }
}

// ---------------- forward row FFT: warp-per-transform, 8 transforms/block --------------
// 130*384 = 49920 row-pair transforms, 8 per block -> 6240 blocks.
__global__ __launch_bounds__(256) void fft_rows_fwd_packed(){
    __shared__ float2 xin[8][NP], As[8][NP], tws[NP];
    int tid = threadIdx.x;
    int w = tid >> 5, lane = tid & 31;
    for (int i=tid;i<NP;i+=256) tws[i]=g_tw[i];
    __syncthreads();
    int g = blockIdx.x*8 + w;
    int ch = g/130, pair = g - 130*ch;
    int r0 = 2*pair, r1 = r0+1;
    int s0 = min(max(r0-2,0),HH-1), s1 = min(max(r1-2,0),HH-1);
    const float* p0r = g_h1 + ((size_t)ch*HH + s0)*WW;
    const float* p1r = g_h1 + ((size_t)ch*HH + s1)*WW;
    float2* xw = xin[w];
    float2* Aw = As[w];
    for (int i=lane;i<NP;i+=32){
        int sc = min(max(i-2,0),WW-1);
        xw[i] = make_float2(p0r[sc], p1r[sc]);
    }
    __syncwarp();
    stageA2(xw, Aw, tws, lane, 32, false);
    __syncwarp();
    for (int q=lane;q<65;q+=32){
        float2 X[4];
        stageC2_quad(Aw, tws, q, false, X);
        xw[q]      = X[0];
        xw[q+65]   = X[1];
        xw[q+130]  = X[2];
        xw[q+195]  = X[3];
    }
    __syncwarp();
    float2* o0 = g_spec + ((size_t)ch*260 + r0)*SW;
    float2* o1 = g_spec + ((size_t)ch*260 + r1)*SW;
    for (int k=lane;k<=130;k+=32){
        float2 Zk = xw[k];
        float2 Zm = xw[(260-k)%260];
        // unpack: A=(Z[k]+conj(Z[-k]))/2, B=(Z[k]-conj(Z[-k]))/(2i)
        o0[k] = make_float2(0.5f*(Zk.x+Zm.x), 0.5f*(Zk.y-Zm.y));
        o1[k] = make_float2(0.5f*(Zk.y+Zm.y), 0.5f*(Zm.x-Zk.x));
    }
}

// ---------------- fused column pass: fwd col FFT + filter + inv col FFT ----------------
__global__ void fft_cols_fused(){
    int k0 = blockIdx.x*8;   // 17 blocks cover 131 columns
    int ch = blockIdx.y;
    __shared__ float2 cs[8][NP];
    __shared__ float2 As2[8][NP];
    __shared__ float2 tws[NP];
    __shared__ float ws[10];
    int tid = threadIdx.x;   // 256
    for (int i=tid;i<NP;i+=256) tws[i]=g_tw[i];
    {
        int c2ch = ch % C2;
        if (tid<9) ws[tid]=g_w9[c2ch*9+tid];
        if (tid==9) ws[9]=g_sig[c2ch];
    }
    float2* base = g_spec + (size_t)ch*260*SW + k0;
    int ncols = 131 - k0; if (ncols>8) ncols=8;
    __syncthreads();
    for (int idx=tid; idx<260*8; idx+=256){
        int r=idx>>3, c=idx&7;
        if (c<ncols) cs[c][r] = base[(size_t)r*SW + c];
    }
    __syncthreads();
    int c = tid>>5, lane = tid&31;
    if (c < ncols){
        // ---- forward column FFT ----
        stageA2(cs[c], As2[c], tws, lane, 32, false);
        __syncwarp();
        int k = k0 + c;
        float2 ev = tws[k];
        float2 rp0 = make_float2(ws[0]*ev.x + ws[1] + ws[2]*ev.x, -ws[0]*ev.y + ws[2]*ev.y);
        float2 rp1 = make_float2(ws[3]*ev.x + ws[4] + ws[5]*ev.x, -ws[3]*ev.y + ws[5]*ev.y);
        float2 rp2 = make_float2(ws[6]*ev.x + ws[7] + ws[8]*ev.x, -ws[6]*ev.y + ws[8]*ev.y);
        float sg = ws[9];
        for (int q=lane;q<65;q+=32){
            float2 X[4];
            stageC2_quad(As2[c], tws, q, false, X);
            #pragma unroll
            for (int j=0;j<4;j++){
                int u = q + 65*j;
                float2 eu = tws[u];
                // FB = conj(eu)*rp0 + rp1 + eu*rp2
                float fbx = eu.x*rp0.x + eu.y*rp0.y + rp1.x + eu.x*rp2.x - eu.y*rp2.y;
                float fby = eu.x*rp0.y - eu.y*rp0.x + rp1.y + eu.x*rp2.y + eu.y*rp2.x;
                float denom = fbx*fbx + fby*fby + sg;
                float scale = 1.0f/(SPECN_F*denom);
                float hx = (fbx+sg)*scale, hy = -fby*scale;
                float2 a = X[j];
                cs[c][u] = make_float2(a.x*hx - a.y*hy, a.x*hy + a.y*hx);
            }
        }
        __syncwarp();
        // ---- inverse column FFT ----
        stageA2(cs[c], As2[c], tws, lane, 32, true);
        __syncwarp();
        for (int q=lane;q<65;q+=32){
            float2 X[4];
            stageC2_quad(As2[c], tws, q, true, X);
            cs[c][q]     = X[0];
            cs[c][q+65]  = X[1];
            cs[c][q+130] = X[2];
            cs[c][q+195] = X[3];
        }
    }
    __syncthreads();
    for (int idx=tid; idx<260*8; idx+=256){
        int r=idx>>3, cc=idx&7;
        if (cc<ncols) base[(size_t)r*SW + cc] = cs[cc][r];
    }
}

// ---------------- inverse row FFT: warp-per-transform, 8 transforms/block --------------
// 128*384 = 49152 transforms, 8 per block -> 6144 blocks.
// spec[ch][u][k] = Y_u[k]; missing k>130 half from SAME row: Y_u[k] = conj(Y_u[260-k]).
__global__ __launch_bounds__(256) void fft_rows_inv_packed(){
    __shared__ float2 zin[8][NP], As[8][NP], tws[NP];
    int tid = threadIdx.x;
    int w = tid >> 5, lane = tid & 31;
    for (int i=tid;i<NP;i+=256) tws[i]=g_tw[i];
    __syncthreads();
    int g = blockIdx.x*8 + w;
    int ch = g/128, pair = g - 128*ch;
    int u0 = 2 + 2*pair, u1 = u0+1;   // padded output rows
    const float2* su0 = g_spec + ((size_t)ch*260 + u0)*SW;
    const float2* su1 = g_spec + ((size_t)ch*260 + u1)*SW;
    float2* zw = zin[w];
    float2* Aw = As[w];
    // z[k] = Y_u0[k] + i*Y_u1[k]
    for (int k=lane;k<=130;k+=32){
        float2 a = su0[k], b = su1[k];
        zw[k] = make_float2(a.x - b.y, a.y + b.x);
    }
    for (int k=131+lane;k<260;k+=32){
        float2 a = su0[260-k], b = su1[260-k];
        zw[k] = make_float2(a.x + b.y, b.x - a.y);
    }
    __syncwarp();
    stageA2(zw, Aw, tws, lane, 32, true);
    __syncwarp();
    for (int q=lane;q<65;q+=32){
        float2 X[4];
        stageC2_quad(Aw, tws, q, true, X);
        zw[q]     = X[0];
        zw[q+65]  = X[1];
        zw[q+130] = X[2];
        zw[q+195] = X[3];
    }
    __syncwarp();
    float* o0 = g_h1 + ((size_t)ch*HH + (u0-2))*WW;
    float* o1 = g_h1 + ((size_t)ch*HH + (u1-2))*WW;
    for (int jj=lane;jj<WW;jj+=32){
        float2 y = zw[jj+2];
        o0[jj] = gelu_f(y.x);
        o1[jj] = gelu_f(y.y);
    }
}

// ---------------- launcher: kernel launches ONLY ----------------
extern "C" void kernel_launch(void* const* d_in, const int* in_sizes, int n_in,
                              void* d_out, int out_size){
    const float* x         = (const float*)d_in[0];
    const float* ln1_w     = (const float*)d_in[1];
    const float* ln1_b     = (const float*)d_in[2];
    const float* w1a       = (const float*)d_in[3];
    const float* b1a       = (const float*)d_in[4];
    const float* conv_w    = (const float*)d_in[5];
    const float* conv_sig  = (const float*)d_in[6];
    const float* w1b       = (const float*)d_in[7];
    const float* b1b       = (const float*)d_in[8];
    const float* ln2_w     = (const float*)d_in[9];
    const float* ln2_b     = (const float*)d_in[10];
    const float* w2a       = (const float*)d_in[11];
    const float* b2a       = (const float*)d_in[12];
    const float* w2b       = (const float*)d_in[13];
    const float* b2b       = (const float*)d_in[14];
    float* out = (float*)d_out;

    init_kernel<<<1, 260>>>(conv_w, conv_sig, w1a, ln1_w, ln1_b, w2a, ln2_w, ln2_b);

    // branch 1: LN(stats) -> expand+gelu (LN folded into W/epilogue) -> converse2d -> gelu
    //           -> project + residual
    ln_stats<-1><<<(BB*PIX)/256, 256>>>(x);
    gemm_kernel<CC, C2, 64, 8, 0, 0, 0, -1, -1, 1><<<dim3(PIX/128, C2/64, BB), 128>>>(
        x, nullptr, b1a, nullptr, nullptr);

    fft_rows_fwd_packed<<<130*NCH/8, 256>>>();
    fft_cols_fused<<<dim3(17, NCH), 256>>>();
    fft_rows_inv_packed<<<128*NCH/8, 256>>>();

    gemm_kernel<C2, CC, 32, 4, 1, -1, 0, 1, -1, 2><<<dim3(PIX/128, CC/32, BB), 128>>>(
        nullptr, w1b, b1b, x, nullptr);

    // branch 2: LN(stats) -> expand+gelu (LN folded) -> project + residual
    ln_stats<2><<<(BB*PIX)/256, 256>>>(nullptr);
    gemm_kernel<CC, C2, 64, 8, 0, 1, 1, 2, -1, 1><<<dim3(PIX/128, C2/64, BB), 128>>>(
        nullptr, nullptr, b2a, nullptr, nullptr);
    gemm_kernel<C2, CC, 32, 4, 1, -1, 0, 1, 2, -1><<<dim3(PIX/128, CC/32, BB), 128>>>(
        nullptr, w2b, b2b, nullptr, out);
}

// round 16
// speedup vs baseline: 1.7000x; 1.2174x over previous
#include <cuda_runtime.h>
#include <math.h>

// ---------------- problem constants ----------------
#define BB 2
#define CC 96
#define C2 192
#define HH 256
#define WW 256
#define PIX (HH*WW)          // 65536
#define NP 260               // padded size (256 + 2*2)
#define SW 132               // spectral row stride (131 stored, Hermitian half)
#define NCH (BB*C2)          // 384
#define SPECN_F 67600.0f     // 260*260

// ---------------- scratch (static device globals; no runtime alloc) -------------
__device__ float  g_h1[(size_t)BB*C2*PIX];
__device__ float  g_x2[(size_t)BB*CC*PIX];
__device__ float2 g_spec[(size_t)NCH*260*SW];    // ~105 MB (half-spectrum)
__device__ float  g_mls[(size_t)BB*PIX];         // per-pixel -mu*rstd
__device__ float  g_rs[(size_t)BB*PIX];          // per-pixel rsqrt(var+eps)
__device__ float2 g_tw[NP];                      // e^{-2*pi*i*n/260}
__device__ float  g_w9[C2*9];
__device__ float  g_sig[C2];
__device__ float  g_wpA[C2*CC];                  // w1a * ln1_w (folded)
__device__ float  g_wpB[C2*CC];                  // w2a * ln2_w (folded)
__device__ float  g_sA1[C2], g_sA2[C2];          // S1 = sum W', S2 = sum W*lnb
__device__ float  g_sB1[C2], g_sB2[C2];

// DFT-13 constants: C13[m]=cos(2*pi*m/13), SN13[m]=sin(2*pi*m/13)
// __device__ constexpr: visible in device code; all uses have compile-time
// indices (fully unrolled), so they fold to FFMA immediates.
__device__ constexpr float C13[13] = {
    1.0f,
    0.88545602565320989f,  0.56806474673115586f,  0.12053668025532305f,
   -0.35460488704253563f, -0.74851074817110109f, -0.97094181742605202f,
   -0.97094181742605202f, -0.74851074817110109f, -0.35460488704253563f,
    0.12053668025532305f,  0.56806474673115586f,  0.88545602565320989f
};
__device__ constexpr float SN13[13] = {
    0.0f,
    0.46472317204376856f,  0.82298386589365639f,  0.99270887409805397f,
    0.93501624268541482f,  0.66312265824079520f,  0.23931566428755777f,
   -0.23931566428755777f, -0.66312265824079520f, -0.93501624268541482f,
   -0.99270887409805397f, -0.82298386589365639f, -0.46472317204376856f
};

// compile-time buffer selector: 1=g_h1, 2=g_x2, -1=external pointer
template<int SEL>
__device__ __forceinline__ float* gbuf(const float* ext){
    if (SEL == 1) return g_h1;
    if (SEL == 2) return g_x2;
    return (float*)ext;
}
template<int SEL>
__device__ __forceinline__ const float* wbuf(const float* ext){
    if (SEL == 0) return g_wpA;
    if (SEL == 1) return g_wpB;
    return ext;
}

__device__ __forceinline__ float gelu_f(float x){
    return 0.5f * x * (1.0f + erff(x * 0.70710678118654752440f));
}

// ---------------- packed f32x2 FMA (Blackwell dual-FMA pipe) ----------------
__device__ __forceinline__ void fma_f32x2(unsigned long long& d,
                                          unsigned long long a,
                                          unsigned long long b){
    asm("fma.rn.f32x2 %0, %1, %2, %0;" : "+l"(d) : "l"(a), "l"(b));
}
__device__ __forceinline__ unsigned long long pack_dup(float x){
    unsigned long long r;
    asm("mov.b64 %0, {%1, %1};" : "=l"(r) : "f"(x));
    return r;
}
__device__ __forceinline__ void unpack2(unsigned long long v, float& lo, float& hi){
    asm("mov.b64 {%0, %1}, %2;" : "=f"(lo), "=f"(hi) : "l"(v));
}

// ---------------- cp.async helpers ----------------
__device__ __forceinline__ void cp_async16(void* dst, const void* src){
    unsigned s = (unsigned)__cvta_generic_to_shared(dst);
    asm volatile("cp.async.cg.shared.global [%0], [%1], 16;" :: "r"(s), "l"(src));
}
__device__ __forceinline__ void cp_commit(){
    asm volatile("cp.async.commit_group;");
}
template<int N>
__device__ __forceinline__ void cp_wait(){
    asm volatile("cp.async.wait_group %0;" :: "n"(N));
}

// ---------------- complex helpers ----------------
__device__ __forceinline__ float2 cmul(float2 a, float2 b){
    return make_float2(a.x*b.x - a.y*b.y, a.x*b.y + a.y*b.x);
}
__device__ __forceinline__ float2 cmac(float2 s, float2 a, float2 t){
    s.x += a.x*t.x - a.y*t.y;
    s.y += a.x*t.y + a.y*t.x;
    return s;
}
__device__ __forceinline__ float2 cadd(float2 a, float2 b){ return make_float2(a.x+b.x, a.y+b.y); }
__device__ __forceinline__ float2 csub(float2 a, float2 b){ return make_float2(a.x-b.x, a.y-b.y); }

// ---------------- init: twiddles + filter params + folded LN weights ----------------
__global__ void init_kernel(const float* __restrict__ conv_w,
                            const float* __restrict__ conv_sigma,
                            const float* __restrict__ w1a,
                            const float* __restrict__ ln1_w,
                            const float* __restrict__ ln1_b,
                            const float* __restrict__ w2a,
                            const float* __restrict__ ln2_w,
                            const float* __restrict__ ln2_b){
    int tid = threadIdx.x;
    if (tid < NP){
        double ang = -2.0 * 3.14159265358979323846 * (double)tid / (double)NP;
        double s, c;
        sincos(ang, &s, &c);
        g_tw[tid] = make_float2((float)c, (float)s);
    }
    for (int ch = tid; ch < C2; ch += blockDim.x){
        float w[9];
        float m = -1e30f;
        #pragma unroll
        for (int i=0;i<9;i++){ w[i] = conv_w[ch*9+i]; m = fmaxf(m, w[i]); }
        float ssum = 0.f;
        #pragma unroll
        for (int i=0;i<9;i++){ w[i] = expf(w[i]-m); ssum += w[i]; }
        float inv = 1.f/ssum;
        #pragma unroll
        for (int i=0;i<9;i++) g_w9[ch*9+i] = w[i]*inv;
        float sp = conv_sigma[ch];
        g_sig[ch] = 1.f/(1.f + expf(9.f - sp)) + 1e-5f;
        // folded LN weights for the two expansion GEMMs
        float s1a=0.f, s2a=0.f, s1b=0.f, s2b=0.f;
        for (int c=0;c<CC;c++){
            float wa = w1a[ch*CC+c];
            float wpa = wa*ln1_w[c];
            g_wpA[ch*CC+c] = wpa;
            s1a += wpa; s2a += wa*ln1_b[c];
            float wb = w2a[ch*CC+c];
            float wpb = wb*ln2_w[c];
            g_wpB[ch*CC+c] = wpb;
            s1b += wpb; s2b += wb*ln2_b[c];
        }
        g_sA1[ch]=s1a; g_sA2[ch]=s2a;
        g_sB1[ch]=s1b; g_sB2[ch]=s2b;
    }
}

// ---------------- LN statistics: per-pixel -mu*rstd & rstd over channels -------------
template<int XSEL>
__global__ void ln_stats(const float* __restrict__ xext){
    const float* x = gbuf<XSEL>(xext);
    int pi = blockIdx.x*blockDim.x + threadIdx.x;
    if (pi >= BB*PIX) return;
    int bb = pi >> 16;
    int p  = pi & (PIX-1);
    const float* xb = x + (size_t)bb*CC*PIX + p;
    float s=0.f, s2=0.f;
    #pragma unroll 4
    for (int c=0;c<CC;c++){ float v = xb[(size_t)c*PIX]; s += v; s2 += v*v; }
    float mu  = s * (1.f/CC);
    float var = s2 * (1.f/CC) - mu*mu;
    float rs  = rsqrtf(var + 1e-5f);
    g_rs[pi]  = rs;
    g_mls[pi] = -mu*rs;
}

// ---------------- 1x1 conv as SGEMM: FFMA2 inner loop, cp.async double-buffered X ----
// MODE 0 (expansion, LN folded): out = gelu(rs[p]*acc + mls[p]*S1[o] + S2[o] + bias[o])
// MODE 1 (projection):           out = acc + bias[o] + res
template<int CIN, int COUT, int BN, int TN, int MODE, int WSEL, int SSEL,
         int XSEL, int RSEL, int OSEL>
__global__ __launch_bounds__(128) void gemm_kernel(
                            const float* __restrict__ Xext,
                            const float* __restrict__ Wext,
                            const float* __restrict__ bias,
                            const float* __restrict__ Rext,
                            float* __restrict__ Oext){
    const float* X   = gbuf<XSEL>(Xext);
    const float* res = gbuf<RSEL>(Rext);
    float*       out = gbuf<OSEL>(Oext);
    const float* Wsrc = wbuf<WSEL>(Wext);
    const int BM=128, BK=16, NCHK=CIN/BK, WP=BN+4, J2=TN/2;
    __shared__ __align__(16) float Xs[2][BK][BM];
    __shared__ __align__(16) float Wall[CIN][WP];
    int bb = blockIdx.z;
    int p0 = blockIdx.x*BM;
    int o0 = blockIdx.y*BN;
    int tid = threadIdx.x;       // 128
    int tx = tid & 15;           // pixel group
    int ty = tid >> 4;           // output group (TN outs)
    unsigned long long accp[J2][8];
    #pragma unroll
    for (int jp=0;jp<J2;jp++)
        #pragma unroll
        for (int i=0;i<8;i++) accp[jp][i]=0ULL;

    const float* Xb = X + (size_t)bb*CIN*PIX + p0;

    // prefetch chunk 0 (cp.async), then stage the whole W slab
    #pragma unroll
    for (int ii=0; ii<4; ii++){
        int idx = tid + 128*ii;
        int k = idx >> 5, c4 = idx & 31;
        cp_async16(&Xs[0][k][c4*4], Xb + (size_t)k*PIX + c4*4);
    }
    cp_commit();
    for (int idx=tid; idx<CIN*BN; idx+=128){
        int o = idx / CIN, k = idx - o*CIN;
        Wall[k][o] = Wsrc[(size_t)(o0+o)*CIN + k];
    }

    for (int c=0; c<NCHK; c++){
        int cur = c & 1;
        if (c+1 < NCHK){
            const float* Xc = Xb + (size_t)(c+1)*BK*PIX;
            #pragma unroll
            for (int ii=0; ii<4; ii++){
                int idx = tid + 128*ii;
                int k = idx >> 5, c4 = idx & 31;
                cp_async16(&Xs[cur^1][k][c4*4], Xc + (size_t)k*PIX + c4*4);
            }
            cp_commit();
            cp_wait<1>();
        } else {
            cp_wait<0>();
        }
        __syncthreads();
        #pragma unroll
        for (int k=0;k<BK;k++){
            int kg = c*BK + k;
            float4 x0 = *(const float4*)&Xs[cur][k][tx*4];        // conflict-free
            float4 x1 = *(const float4*)&Xs[cur][k][64 + tx*4];   // conflict-free
            unsigned long long xp[8];
            xp[0]=pack_dup(x0.x); xp[1]=pack_dup(x0.y);
            xp[2]=pack_dup(x0.z); xp[3]=pack_dup(x0.w);
            xp[4]=pack_dup(x1.x); xp[5]=pack_dup(x1.y);
            xp[6]=pack_dup(x1.z); xp[7]=pack_dup(x1.w);
            unsigned long long wp[J2];
            #pragma unroll
            for (int jp=0;jp<J2;jp++)
                wp[jp] = *(const unsigned long long*)&Wall[kg][ty*TN + 2*jp];
            #pragma unroll
            for (int jp=0;jp<J2;jp++)
                #pragma unroll
                for (int i=0;i<8;i++)
                    fma_f32x2(accp[jp][i], xp[i], wp[jp]);
        }
        __syncthreads();
    }

    // unpack accumulators
    float acc[TN][8];
    #pragma unroll
    for (int jp=0;jp<J2;jp++)
        #pragma unroll
        for (int i=0;i<8;i++)
            unpack2(accp[jp][i], acc[2*jp][i], acc[2*jp+1][i]);

    float rsv[8], mlv[8];
    if (MODE==0){
        size_t sb = (size_t)bb*PIX + p0;
        float4 r0 = *(const float4*)(g_rs  + sb + tx*4);
        float4 r1 = *(const float4*)(g_rs  + sb + 64 + tx*4);
        float4 m0 = *(const float4*)(g_mls + sb + tx*4);
        float4 m1 = *(const float4*)(g_mls + sb + 64 + tx*4);
        rsv[0]=r0.x; rsv[1]=r0.y; rsv[2]=r0.z; rsv[3]=r0.w;
        rsv[4]=r1.x; rsv[5]=r1.y; rsv[6]=r1.z; rsv[7]=r1.w;
        mlv[0]=m0.x; mlv[1]=m0.y; mlv[2]=m0.z; mlv[3]=m0.w;
        mlv[4]=m1.x; mlv[5]=m1.y; mlv[6]=m1.z; mlv[7]=m1.w;
    }
    const float* S1 = (SSEL==0) ? g_sA1 : g_sB1;
    const float* S2 = (SSEL==0) ? g_sA2 : g_sB2;
    #pragma unroll
    for (int j=0;j<TN;j++){
        int o = o0 + ty*TN + j;
        float bj = bias[o];
        size_t ob = ((size_t)(bb*COUT + o))*PIX + p0;
        size_t oidx0 = ob + tx*4;
        size_t oidx1 = ob + 64 + tx*4;
        float v[8];
        if (MODE==0){
            float s1 = S1[o], s2 = S2[o];
            #pragma unroll
            for (int i=0;i<8;i++)
                v[i] = gelu_f(rsv[i]*acc[j][i] + mlv[i]*s1 + s2 + bj);
        } else {
            float4 r0 = *(const float4*)(res + oidx0);
            float4 r1 = *(const float4*)(res + oidx1);
            v[0]=acc[j][0]+bj+r0.x; v[1]=acc[j][1]+bj+r0.y;
            v[2]=acc[j][2]+bj+r0.z; v[3]=acc[j][3]+bj+r0.w;
            v[4]=acc[j][4]+bj+r1.x; v[5]=acc[j][5]+bj+r1.y;
            v[6]=acc[j][6]+bj+r1.z; v[7]=acc[j][7]+bj+r1.w;
        }
        *(float4*)(out + oidx0) = make_float4(v[0],v[1],v[2],v[3]);
        *(float4*)(out + oidx1) = make_float4(v[4],v[5],v[6],v[7]);
    }
}

// ---------------- FFT core: 260 = 20 x 13 (13-pt DFTs then radix-4 20-pt stage) --------
// Stage A (13-pt DFTs, one per b<20): A2[13b+k2] = sum_{a<13} z[20a+b] * W13^{a*k2}.
// Constant-coefficient conjugate-pair factorization: u_a = z_a+z_{13-a}, v_a = z_a-z_{13-a};
// X[k] = (z0.re+P-Q, z0.im+R+S), X[13-k] = (z0.re+P+Q, z0.im+R-S), with
// P=sum c*u.re, Q=sum s*v.im, R=sum c*u.im, S=sum s*v.re; c,s compile-time immediates.
// One thread per b (lanes 0..19 active; idle lanes cost no issue slots).
template<int INVI>
__device__ __forceinline__ void stageA2_13(const float2* __restrict__ z,
                                           float2* __restrict__ A2,
                                           int lane){
    if (lane < 20){
        int b = lane;
        float2 zz[13];
        #pragma unroll
        for (int a=0;a<13;a++) zz[a] = z[20*a + b];
        float2 u[7], v[7];
        #pragma unroll
        for (int a=1;a<=6;a++){
            u[a] = cadd(zz[a], zz[13-a]);
            v[a] = csub(zz[a], zz[13-a]);
        }
        float2* outp = A2 + 13*b;
        float2 a0 = zz[0];
        #pragma unroll
        for (int a=1;a<=6;a++) a0 = cadd(a0, u[a]);
        outp[0] = a0;
        #pragma unroll
        for (int k=1;k<=6;k++){
            float P=0.f, Q=0.f, R=0.f, S=0.f;
            #pragma unroll
            for (int a=1;a<=6;a++){
                const int m = (a*k)%13;
                const float c = C13[m];
                const float s = INVI ? SN13[m] : -SN13[m];
                P += c*u[a].x;
                Q += s*v[a].y;
                R += c*u[a].y;
                S += s*v[a].x;
            }
            outp[k]    = make_float2(zz[0].x + P - Q, zz[0].y + R + S);
            outp[13-k] = make_float2(zz[0].x + P + Q, zz[0].y + R - S);
        }
    }
}

// compute outputs X[q + 65j], j=0..3 (radix-4 over b: W260^65 = -i)
__device__ __forceinline__ void stageC2_quad(const float2* __restrict__ A2,
                                             const float2* __restrict__ tws,
                                             int q, bool inv, float2 X[4]){
    int k2 = q % 13;
    float2 t1 = tws[q]; if (inv) t1.y = -t1.y;
    float2 t2 = cmul(t1,t1);
    float2 u  = cmul(t2,t2);     // t1^4
    float2 S0=make_float2(0,0), S1=make_float2(0,0), S2=make_float2(0,0), S3=make_float2(0,0);
    float2 t = make_float2(1.f,0.f);
    #pragma unroll
    for (int m=0;m<5;m++){
        const float2* base = A2 + (4*m)*13 + k2;
        float2 v0 = base[0], v1 = base[13], v2 = base[26], v3 = base[39];
        S0 = cmac(S0, v0, t);
        S1 = cmac(S1, v1, t);
        S2 = cmac(S2, v2, t);
        S3 = cmac(S3, v3, t);
        t = cmul(t, u);
    }
    float2 T1 = cmul(t1, S1);
    float2 T2 = cmul(t2, S2);
    float2 t3 = cmul(t2, t1);
    float2 T3 = cmul(t3, S3);
    float2 E0 = cadd(S0, T2), E1 = csub(S0, T2);
    float2 O0 = cadd(T1, T3), O1 = csub(T1, T3);
    X[0] = cadd(E0, O0);
    X[2] = csub(E0, O0);
    if (!inv){   // omega = -i
        X[1] = make_float2(E1.x + O1.y, E1.y - O1.x);
        X[3] = make_float2(E1.x - O1.y, E1.y + O1.x);
    } else {     // omega = +i
        X[1] = make_float2(E1.x - O1.y, E1.y + O1.x);
        X[3] = make_float2(E1.x + O1.y, E1.y - O1.x);
    }
}

// ---------------- forward row FFT: warp-per-transform, 8 transforms/block --------------
__global__ __launch_bounds__(256) void fft_rows_fwd_packed(){
    __shared__ float2 xin[8][NP], As[8][NP], tws[NP];
    int tid = threadIdx.x;
    int w = tid >> 5, lane = tid & 31;
    for (int i=tid;i<NP;i+=256) tws[i]=g_tw[i];
    __syncthreads();
    int g = blockIdx.x*8 + w;
    int ch = g/130, pair = g - 130*ch;
    int r0 = 2*pair, r1 = r0+1;
    int s0 = min(max(r0-2,0),HH-1), s1 = min(max(r1-2,0),HH-1);
    const float* p0r = g_h1 + ((size_t)ch*HH + s0)*WW;
    const float* p1r = g_h1 + ((size_t)ch*HH + s1)*WW;
    float2* xw = xin[w];
    float2* Aw = As[w];
    for (int i=lane;i<NP;i+=32){
        int sc = min(max(i-2,0),WW-1);
        xw[i] = make_float2(p0r[sc], p1r[sc]);
    }
    __syncwarp();
    stageA2_13<0>(xw, Aw, lane);
    __syncwarp();
    for (int q=lane;q<65;q+=32){
        float2 X[4];
        stageC2_quad(Aw, tws, q, false, X);
        xw[q]      = X[0];
        xw[q+65]   = X[1];
        xw[q+130]  = X[2];
        xw[q+195]  = X[3];
    }
    __syncwarp();
    float2* o0 = g_spec + ((size_t)ch*260 + r0)*SW;
    float2* o1 = g_spec + ((size_t)ch*260 + r1)*SW;
    for (int k=lane;k<=130;k+=32){
        float2 Zk = xw[k];
        float2 Zm = xw[(260-k)%260];
        // unpack: A=(Z[k]+conj(Z[-k]))/2, B=(Z[k]-conj(Z[-k]))/(2i)
        o0[k] = make_float2(0.5f*(Zk.x+Zm.x), 0.5f*(Zk.y-Zm.y));
        o1[k] = make_float2(0.5f*(Zk.y+Zm.y), 0.5f*(Zm.x-Zk.x));
    }
}

// ---------------- fused column pass: fwd col FFT + filter + inv col FFT ----------------
__global__ void fft_cols_fused(){
    int k0 = blockIdx.x*8;   // 17 blocks cover 131 columns
    int ch = blockIdx.y;
    __shared__ float2 cs[8][NP];
    __shared__ float2 As2[8][NP];
    __shared__ float2 tws[NP];
    __shared__ float ws[10];
    int tid = threadIdx.x;   // 256
    for (int i=tid;i<NP;i+=256) tws[i]=g_tw[i];
    {
        int c2ch = ch % C2;
        if (tid<9) ws[tid]=g_w9[c2ch*9+tid];
        if (tid==9) ws[9]=g_sig[c2ch];
    }
    float2* base = g_spec + (size_t)ch*260*SW + k0;
    int ncols = 131 - k0; if (ncols>8) ncols=8;
    __syncthreads();
    for (int idx=tid; idx<260*8; idx+=256){
        int r=idx>>3, c=idx&7;
        if (c<ncols) cs[c][r] = base[(size_t)r*SW + c];
    }
    __syncthreads();
    int c = tid>>5, lane = tid&31;
    if (c < ncols){
        // ---- forward column FFT ----
        stageA2_13<0>(cs[c], As2[c], lane);
        __syncwarp();
        int k = k0 + c;
        float2 ev = tws[k];
        float2 rp0 = make_float2(ws[0]*ev.x + ws[1] + ws[2]*ev.x, -ws[0]*ev.y + ws[2]*ev.y);
        float2 rp1 = make_float2(ws[3]*ev.x + ws[4] + ws[5]*ev.x, -ws[3]*ev.y + ws[5]*ev.y);
        float2 rp2 = make_float2(ws[6]*ev.x + ws[7] + ws[8]*ev.x, -ws[6]*ev.y + ws[8]*ev.y);
        float sg = ws[9];
        for (int q=lane;q<65;q+=32){
            float2 X[4];
            stageC2_quad(As2[c], tws, q, false, X);
            #pragma unroll
            for (int j=0;j<4;j++){
                int u = q + 65*j;
                float2 eu = tws[u];
                // FB = conj(eu)*rp0 + rp1 + eu*rp2
                float fbx = eu.x*rp0.x + eu.y*rp0.y + rp1.x + eu.x*rp2.x - eu.y*rp2.y;
                float fby = eu.x*rp0.y - eu.y*rp0.x + rp1.y + eu.x*rp2.y + eu.y*rp2.x;
                float denom = fbx*fbx + fby*fby + sg;
                float scale = 1.0f/(SPECN_F*denom);
                float hx = (fbx+sg)*scale, hy = -fby*scale;
                float2 a = X[j];
                cs[c][u] = make_float2(a.x*hx - a.y*hy, a.x*hy + a.y*hx);
            }
        }
        __syncwarp();
        // ---- inverse column FFT ----
        stageA2_13<1>(cs[c], As2[c], lane);
        __syncwarp();
        for (int q=lane;q<65;q+=32){
            float2 X[4];
            stageC2_quad(As2[c], tws, q, true, X);
            cs[c][q]     = X[0];
            cs[c][q+65]  = X[1];
            cs[c][q+130] = X[2];
            cs[c][q+195] = X[3];
        }
    }
    __syncthreads();
    for (int idx=tid; idx<260*8; idx+=256){
        int r=idx>>3, cc=idx&7;
        if (cc<ncols) base[(size_t)r*SW + cc] = cs[cc][r];
    }
}

// ---------------- inverse row FFT: warp-per-transform, 8 transforms/block --------------
// spec[ch][u][k] = Y_u[k]; missing k>130 half from SAME row: Y_u[k] = conj(Y_u[260-k]).
__global__ __launch_bounds__(256) void fft_rows_inv_packed(){
    __shared__ float2 zin[8][NP], As[8][NP], tws[NP];
    int tid = threadIdx.x;
    int w = tid >> 5, lane = tid & 31;
    for (int i=tid;i<NP;i+=256) tws[i]=g_tw[i];
    __syncthreads();
    int g = blockIdx.x*8 + w;
    int ch = g/128, pair = g - 128*ch;
    int u0 = 2 + 2*pair, u1 = u0+1;   // padded output rows
    const float2* su0 = g_spec + ((size_t)ch*260 + u0)*SW;
    const float2* su1 = g_spec + ((size_t)ch*260 + u1)*SW;
    float2* zw = zin[w];
    float2* Aw = As[w];
    // z[k] = Y_u0[k] + i*Y_u1[k]
    for (int k=lane;k<=130;k+=32){
        float2 a = su0[k], b = su1[k];
        zw[k] = make_float2(a.x - b.y, a.y + b.x);
    }
    for (int k=131+lane;k<260;k+=32){
        float2 a = su0[260-k], b = su1[260-k];
        zw[k] = make_float2(a.x + b.y, b.x - a.y);
    }
    __syncwarp();
    stageA2_13<1>(zw, Aw, lane);
    __syncwarp();
    for (int q=lane;q<65;q+=32){
        float2 X[4];
        stageC2_quad(Aw, tws, q, true, X);
        zw[q]     = X[0];
        zw[q+65]  = X[1];
        zw[q+130] = X[2];
        zw[q+195] = X[3];
    }
    __syncwarp();
    float* o0 = g_h1 + ((size_t)ch*HH + (u0-2))*WW;
    float* o1 = g_h1 + ((size_t)ch*HH + (u1-2))*WW;
    for (int jj=lane;jj<WW;jj+=32){
        float2 y = zw[jj+2];
        o0[jj] = gelu_f(y.x);
        o1[jj] = gelu_f(y.y);
    }
}

// ---------------- launcher: kernel launches ONLY ----------------
extern "C" void kernel_launch(void* const* d_in, const int* in_sizes, int n_in,
                              void* d_out, int out_size){
    const float* x         = (const float*)d_in[0];
    const float* ln1_w     = (const float*)d_in[1];
    const float* ln1_b     = (const float*)d_in[2];
    const float* w1a       = (const float*)d_in[3];
    const float* b1a       = (const float*)d_in[4];
    const float* conv_w    = (const float*)d_in[5];
    const float* conv_sig  = (const float*)d_in[6];
    const float* w1b       = (const float*)d_in[7];
    const float* b1b       = (const float*)d_in[8];
    const float* ln2_w     = (const float*)d_in[9];
    const float* ln2_b     = (const float*)d_in[10];
    const float* w2a       = (const float*)d_in[11];
    const float* b2a       = (const float*)d_in[12];
    const float* w2b       = (const float*)d_in[13];
    const float* b2b       = (const float*)d_in[14];
    float* out = (float*)d_out;

    init_kernel<<<1, 260>>>(conv_w, conv_sig, w1a, ln1_w, ln1_b, w2a, ln2_w, ln2_b);

    // branch 1: LN(stats) -> expand+gelu (LN folded into W/epilogue) -> converse2d -> gelu
    //           -> project + residual
    ln_stats<-1><<<(BB*PIX)/256, 256>>>(x);
    gemm_kernel<CC, C2, 64, 8, 0, 0, 0, -1, -1, 1><<<dim3(PIX/128, C2/64, BB), 128>>>(
        x, nullptr, b1a, nullptr, nullptr);

    fft_rows_fwd_packed<<<130*NCH/8, 256>>>();
    fft_cols_fused<<<dim3(17, NCH), 256>>>();
    fft_rows_inv_packed<<<128*NCH/8, 256>>>();

    gemm_kernel<C2, CC, 32, 4, 1, -1, 0, 1, -1, 2><<<dim3(PIX/128, CC/32, BB), 128>>>(
        nullptr, w1b, b1b, x, nullptr);

    // branch 2: LN(stats) -> expand+gelu (LN folded) -> project + residual
    ln_stats<2><<<(BB*PIX)/256, 256>>>(nullptr);
    gemm_kernel<CC, C2, 64, 8, 0, 1, 1, 2, -1, 1><<<dim3(PIX/128, C2/64, BB), 128>>>(
        nullptr, nullptr, b2a, nullptr, nullptr);
    gemm_kernel<C2, CC, 32, 4, 1, -1, 0, 1, 2, -1><<<dim3(PIX/128, CC/32, BB), 128>>>(
        nullptr, w2b, b2b, nullptr, out);
}